// round 3
// baseline (speedup 1.0000x reference)
#include <cuda_runtime.h>
#include <math.h>

// Problem constants (fixed by the dataset)
#define NMAX   100000
#define EMAX   200000
#define GNUM   64
#define FIN    128
#define HIDDEN 256
#define NFILT  8
#define OUTD   64
#define ATTD   128
#define HEADS  4
#define BN_EPS 1e-5f

// ---------------- scratch (static device globals; no allocation) ----------------
__device__ float g_hx [(size_t)NMAX * ATTD];   // per-head hx (reused across heads)
__device__ float g_y  [(size_t)NMAX * ATTD];   // per-head hx @ A
__device__ float g_h  [(size_t)NMAX * HIDDEN]; // relu(x@W_f1+b_f1)
__device__ float g_x0a[(size_t)NMAX * OUTD];
__device__ float g_x0b[(size_t)NMAX * OUTD];
__device__ float g_x0c[(size_t)NMAX * FIN];
__device__ float g_acc[EMAX];                  // summed head scores per edge
__device__ int   g_segstart[GNUM + 1];
__device__ float g_m1 [GNUM * OUTD];
__device__ float g_xm1[GNUM * OUTD];
__device__ float g_m2 [GNUM * OUTD];
__device__ float g_xm2[GNUM * FIN];
__device__ float g_bnsum[FIN];
__device__ float g_bnsq [FIN];
__device__ float g_mu  [FIN];
__device__ float g_rstd[FIN];

// ---------------- generic tiled SGEMM: C(N x M) = A(N x K) @ B(K x M) ----------------
// EPI: 0 = +bias, 1 = relu(+bias), 2 = relu(+bias - xm[batch[r]]), 3 = +bias - xm[batch[r]]
template<int K, int M, int EPI>
__global__ void gemm_kernel(const float* __restrict__ A, const float* __restrict__ B,
                            const float* __restrict__ bias, const float* __restrict__ xm,
                            const int* __restrict__ batch, float* __restrict__ C, int Nrows)
{
    __shared__ float As[16][64];
    __shared__ float Bs[16][64];

    const int tid = threadIdx.x;           // 256 threads
    const int row0 = blockIdx.x * 64;
    const int col0 = blockIdx.y * 64;

    const int lr = tid >> 2;               // 0..63  A-row in tile
    const int lk = (tid & 3) * 4;          // 0,4,8,12 k offset
    const int bk = tid >> 4;               // 0..15  B-k in tile
    const int bn = (tid & 15) * 4;         // col offset

    const int ty = tid >> 4;               // 0..15
    const int tx = tid & 15;               // 0..15

    float acc[4][4];
#pragma unroll
    for (int i = 0; i < 4; i++)
#pragma unroll
        for (int j = 0; j < 4; j++) acc[i][j] = 0.f;

    for (int k0 = 0; k0 < K; k0 += 16) {
        // load A tile (transposed into As[k][m])
        float4 a4 = make_float4(0.f, 0.f, 0.f, 0.f);
        int ar = row0 + lr;
        if (ar < Nrows) a4 = *(const float4*)&A[(size_t)ar * K + k0 + lk];
        As[lk + 0][lr] = a4.x; As[lk + 1][lr] = a4.y;
        As[lk + 2][lr] = a4.z; As[lk + 3][lr] = a4.w;
        // load B tile
        float4 b4 = *(const float4*)&B[(size_t)(k0 + bk) * M + col0 + bn];
        *(float4*)&Bs[bk][bn] = b4;
        __syncthreads();

#pragma unroll
        for (int k = 0; k < 16; k++) {
            float ra[4], rb[4];
#pragma unroll
            for (int i = 0; i < 4; i++) ra[i] = As[k][ty * 4 + i];
#pragma unroll
            for (int j = 0; j < 4; j++) rb[j] = Bs[k][tx * 4 + j];
#pragma unroll
            for (int i = 0; i < 4; i++)
#pragma unroll
                for (int j = 0; j < 4; j++) acc[i][j] += ra[i] * rb[j];
        }
        __syncthreads();
    }

    const int rbase = row0 + ty * 4;
    const int cbase = col0 + tx * 4;
#pragma unroll
    for (int i = 0; i < 4; i++) {
        int r = rbase + i;
        if (r >= Nrows) continue;
        int bidx = 0;
        if (EPI >= 2) bidx = batch[r];
#pragma unroll
        for (int j = 0; j < 4; j++) {
            int c = cbase + j;
            float v = acc[i][j];
            if (bias) v += bias[c];
            if (EPI >= 2) v -= xm[bidx * M + c];
            if (EPI == 1 || EPI == 2) v = fmaxf(v, 0.f);
            C[(size_t)r * M + c] = v;
        }
    }
}

// ---------------- init / zero ----------------
__global__ void init_zero(int E_)
{
    int i = blockIdx.x * blockDim.x + threadIdx.x;
    if (i < E_) g_acc[i] = 0.f;
    if (i < FIN) { g_bnsum[i] = 0.f; g_bnsq[i] = 0.f; }
}

// ---------------- edge bilinear dot: acc[e] += dot(y[row_e], hx[col_e]) ----------------
__global__ void edge_dot_kernel(const int* __restrict__ ei, int E_)
{
    int w = (blockIdx.x * blockDim.x + threadIdx.x) >> 5;
    int lane = threadIdx.x & 31;
    if (w >= E_) return;
    int r = ei[w];
    int c = ei[E_ + w];
    const float4* yv = (const float4*)(g_y  + (size_t)r * ATTD);
    const float4* hv = (const float4*)(g_hx + (size_t)c * ATTD);
    float4 a = yv[lane], b = hv[lane];
    float s = a.x * b.x + a.y * b.y + a.z * b.z + a.w * b.w;
#pragma unroll
    for (int o = 16; o; o >>= 1) s += __shfl_xor_sync(0xffffffffu, s, o);
    if (lane == 0) g_acc[w] += s;
}

__global__ void att_out_kernel(float* __restrict__ out_att, int E_)
{
    int e = blockIdx.x * blockDim.x + threadIdx.x;
    if (e < E_) out_att[e] = 1.f / (1.f + expf(-0.25f * g_acc[e]));
}

// ---------------- fused fv + first set_fn layer (warp per row) ----------------
// fv = g_h_row @ W_f2 + b_f2 (8); x0a = relu(fv @ Weff + b_l0) where
// Weff[p] = W_l0[2p] + W_l0[2p+1]  (folds the repeat(.,2) )
__global__ void filt2_kernel(const float* __restrict__ W_f2, const float* __restrict__ b_f2,
                             const float* __restrict__ W_l0, const float* __restrict__ b_l0,
                             int Nrows)
{
    __shared__ float sW2[HIDDEN * NFILT];   // 256*8
    __shared__ float sWe[NFILT * OUTD];     // 8*64
    __shared__ float sb2[NFILT];
    __shared__ float sbl[OUTD];

    int tid = threadIdx.x; // 256
    for (int i = tid; i < HIDDEN * NFILT; i += 256) sW2[i] = W_f2[i];
    for (int i = tid; i < NFILT * OUTD; i += 256) {
        int p = i / OUTD, c = i % OUTD;
        sWe[i] = W_l0[(2 * p) * OUTD + c] + W_l0[(2 * p + 1) * OUTD + c];
    }
    if (tid < NFILT) sb2[tid] = b_f2[tid];
    if (tid < OUTD)  sbl[tid] = b_l0[tid];
    __syncthreads();

    int warp = tid >> 5, lane = tid & 31;
    int row = blockIdx.x * 8 + warp;
    if (row >= Nrows) return;

    const float* hrow = g_h + (size_t)row * HIDDEN;
    float f[NFILT];
#pragma unroll
    for (int j = 0; j < NFILT; j++) f[j] = 0.f;
#pragma unroll
    for (int kk = 0; kk < HIDDEN / 32; kk++) {
        float hv = hrow[lane + kk * 32];
        const float* wrow = &sW2[(lane + kk * 32) * NFILT];
#pragma unroll
        for (int j = 0; j < NFILT; j++) f[j] += hv * wrow[j];
    }
#pragma unroll
    for (int o = 16; o; o >>= 1)
#pragma unroll
        for (int j = 0; j < NFILT; j++) f[j] += __shfl_xor_sync(0xffffffffu, f[j], o);
#pragma unroll
    for (int j = 0; j < NFILT; j++) f[j] += sb2[j];

    float* orow = g_x0a + (size_t)row * OUTD;
#pragma unroll
    for (int t = 0; t < 2; t++) {
        int c = lane + t * 32;
        float o = sbl[c];
#pragma unroll
        for (int j = 0; j < NFILT; j++) o += f[j] * sWe[j * OUTD + c];
        orow[c] = fmaxf(o, 0.f);
    }
}

// ---------------- segment boundaries (batch sorted) ----------------
__global__ void segbounds_kernel(const int* __restrict__ batch, int Nrows)
{
    int i = blockIdx.x * blockDim.x + threadIdx.x;
    if (i >= Nrows) return;
    int b = batch[i];
    int prev = (i == 0) ? -1 : batch[i - 1];
    for (int g = prev + 1; g <= b; ++g) g_segstart[g] = i;
    if (i == Nrows - 1)
        for (int g = b + 1; g <= GNUM; ++g) g_segstart[g] = Nrows;
}

// ---------------- segment mean (block per graph) ----------------
template<int C>
__global__ void segmean_kernel(const float* __restrict__ X, float* __restrict__ out)
{
    const int T = 256;
    int g = blockIdx.x;
    int s = g_segstart[g], e = g_segstart[g + 1];
    int tid = threadIdx.x;
    int col = tid % C, rgrp = tid / C;
    const int ngrp = T / C;
    float acc = 0.f;
    for (int r = s + rgrp; r < e; r += ngrp) acc += X[(size_t)r * C + col];
    __shared__ float sh[T];
    sh[tid] = acc;
    __syncthreads();
    if (tid < C) {
        float t = 0.f;
#pragma unroll
        for (int k = 0; k < ngrp; k++) t += sh[tid + k * C];
        float cnt = (float)(e - s);
        out[g * C + tid] = t / fmaxf(cnt, 1.f);
    }
}

// ---------------- small GEMM: C(G x M) = A(G x K) @ B(K x M) ----------------
template<int K, int M>
__global__ void small_gemm(const float* __restrict__ A, const float* __restrict__ B,
                           float* __restrict__ C)
{
    int g = blockIdx.x;
    __shared__ float a[K];
    if (threadIdx.x < K) a[threadIdx.x] = A[g * K + threadIdx.x];
    __syncthreads();
    for (int j = threadIdx.x; j < M; j += blockDim.x) {
        float s = 0.f;
#pragma unroll 8
        for (int k = 0; k < K; k++) s += a[k] * B[k * M + j];
        C[g * M + j] = s;
    }
}

// ---------------- BatchNorm stats over relu(g_x0c) ----------------
__global__ void bn_stats_kernel(int Nrows)
{
    int col = threadIdx.x; // 128
    float s = 0.f, q = 0.f;
    for (int r = blockIdx.x; r < Nrows; r += gridDim.x) {
        float v = fmaxf(g_x0c[(size_t)r * FIN + col], 0.f);
        s += v; q += v * v;
    }
    atomicAdd(&g_bnsum[col], s);
    atomicAdd(&g_bnsq[col], q);
}

__global__ void bn_fin_kernel(int Nrows)
{
    int c = threadIdx.x;
    float inv = 1.f / (float)Nrows;
    float mu = g_bnsum[c] * inv;
    float var = g_bnsq[c] * inv - mu * mu;
    g_mu[c] = mu;
    g_rstd[c] = rsqrtf(var + BN_EPS);
}

// ---------------- final: out = x + (relu(x0c)-mu)*rstd*gamma + beta ----------------
__global__ void final_kernel(const float* __restrict__ x, const float* __restrict__ gamma,
                             const float* __restrict__ beta, float* __restrict__ out, int Nrows)
{
    int i = blockIdx.x * blockDim.x + threadIdx.x;
    if (i >= Nrows * FIN) return;
    int c = i & (FIN - 1);
    float h = fmaxf(g_x0c[i], 0.f);
    out[i] = x[i] + (h - g_mu[c]) * g_rstd[c] * gamma[c] + beta[c];
}

// ============================================================================
extern "C" void kernel_launch(void* const* d_in, const int* in_sizes, int n_in,
                              void* d_out, int out_size)
{
    const float* x       = (const float*)d_in[0];
    const int*   ei      = (const int*)  d_in[1];
    const int*   batch   = (const int*)  d_in[2];
    const float* W_f1    = (const float*)d_in[3];
    const float* b_f1    = (const float*)d_in[4];
    const float* W_f2    = (const float*)d_in[5];
    const float* b_f2    = (const float*)d_in[6];
    const float* W_l0    = (const float*)d_in[7];
    const float* b_l0    = (const float*)d_in[8];
    const float* G1      = (const float*)d_in[9];
    const float* b_g1    = (const float*)d_in[10];
    const float* L1      = (const float*)d_in[11];
    const float* G2      = (const float*)d_in[12];
    const float* b_g2    = (const float*)d_in[13];
    const float* L2      = (const float*)d_in[14];
    const float* bn_gamma= (const float*)d_in[15];
    const float* bn_beta = (const float*)d_in[16];
    const float* W_att   = (const float*)d_in[17];
    const float* b_att   = (const float*)d_in[18];
    const float* A_att   = (const float*)d_in[19];

    const int N = in_sizes[0] / FIN;
    const int E = in_sizes[1] / 2;

    float* out_x   = (float*)d_out;
    float* out_att = (float*)d_out + (size_t)N * FIN;

    float* hx_p  = nullptr; cudaGetSymbolAddress((void**)&hx_p,  g_hx);
    float* y_p   = nullptr; cudaGetSymbolAddress((void**)&y_p,   g_y);
    float* h_p   = nullptr; cudaGetSymbolAddress((void**)&h_p,   g_h);
    float* x0a_p = nullptr; cudaGetSymbolAddress((void**)&x0a_p, g_x0a);
    float* x0b_p = nullptr; cudaGetSymbolAddress((void**)&x0b_p, g_x0b);
    float* x0c_p = nullptr; cudaGetSymbolAddress((void**)&x0c_p, g_x0c);
    float* m1_p  = nullptr; cudaGetSymbolAddress((void**)&m1_p,  g_m1);
    float* xm1_p = nullptr; cudaGetSymbolAddress((void**)&xm1_p, g_xm1);
    float* m2_p  = nullptr; cudaGetSymbolAddress((void**)&m2_p,  g_m2);
    float* xm2_p = nullptr; cudaGetSymbolAddress((void**)&xm2_p, g_xm2);

    const int gemmN = (N + 63) / 64;

    // zero accumulators
    init_zero<<<(E + 255) / 256, 256>>>(E);

    // ---- attention: per head hx = x@W+b ; y = hx@A ; edge dots ----
    for (int h = 0; h < HEADS; h++) {
        gemm_kernel<FIN, ATTD, 0><<<dim3(gemmN, ATTD / 64), 256>>>(
            x, W_att + (size_t)h * FIN * ATTD, b_att + h * ATTD,
            nullptr, nullptr, hx_p, N);
        gemm_kernel<ATTD, ATTD, 0><<<dim3(gemmN, ATTD / 64), 256>>>(
            hx_p, A_att + (size_t)h * ATTD * ATTD, nullptr,
            nullptr, nullptr, y_p, N);
        edge_dot_kernel<<<(E + 7) / 8, 256>>>(ei, E);
    }
    att_out_kernel<<<(E + 255) / 256, 256>>>(out_att, E);

    // ---- filtration MLP ----
    gemm_kernel<FIN, HIDDEN, 1><<<dim3(gemmN, HIDDEN / 64), 256>>>(
        x, W_f1, b_f1, nullptr, nullptr, h_p, N);
    filt2_kernel<<<(N + 7) / 8, 256>>>(W_f2, b_f2, W_l0, b_l0, N);

    // ---- segment structure ----
    segbounds_kernel<<<(N + 255) / 256, 256>>>(batch, N);

    // ---- DeepSet 1 ----
    segmean_kernel<OUTD><<<GNUM, 256>>>(x0a_p, m1_p);
    small_gemm<OUTD, OUTD><<<GNUM, 128>>>(m1_p, L1, xm1_p);
    gemm_kernel<OUTD, OUTD, 2><<<dim3(gemmN, 1), 256>>>(
        x0a_p, G1, b_g1, xm1_p, batch, x0b_p, N);

    // ---- DeepSet 2 ----
    segmean_kernel<OUTD><<<GNUM, 256>>>(x0b_p, m2_p);
    small_gemm<OUTD, FIN><<<GNUM, 128>>>(m2_p, L2, xm2_p);
    gemm_kernel<OUTD, FIN, 3><<<dim3(gemmN, FIN / 64), 256>>>(
        x0b_p, G2, b_g2, xm2_p, batch, x0c_p, N);

    // ---- BatchNorm + residual ----
    bn_stats_kernel<<<512, FIN>>>(N);
    bn_fin_kernel<<<1, FIN>>>(N);
    final_kernel<<<(N * FIN + 255) / 256, 256>>>(x, bn_gamma, bn_beta, out_x, N);
}

// round 6
// speedup vs baseline: 1.7032x; 1.7032x over previous
#include <cuda_runtime.h>
#include <math.h>

// Problem constants (fixed by the dataset)
#define NMAX   100000
#define EMAX   200000
#define GNUM   64
#define FIN    128
#define HIDDEN 256
#define NFILT  8
#define OUTD   64
#define ATTD   128
#define HEADS  4
#define BN_EPS 1e-5f

// ---------------- scratch (static device globals; no allocation) ----------------
__device__ float g_z  [(size_t)NMAX * FIN];    // x @ Msum
__device__ float g_h  [(size_t)NMAX * HIDDEN]; // relu(x@W_f1+b_f1)
__device__ float g_x0a[(size_t)NMAX * OUTD];
__device__ float g_x0b[(size_t)NMAX * OUTD];
__device__ float g_x0c[(size_t)NMAX * FIN];
__device__ float g_ar [NMAX];                  // x·vsum + csum  (row term)
__device__ float g_ac [NMAX];                  // x·usum        (col term)
__device__ float g_T  [HEADS * ATTD * ATTD];   // per-head W@A
__device__ float g_msum[FIN * FIN];            // sum_h W A W^T
__device__ float g_vsum[FIN];
__device__ float g_usum[FIN];
__device__ float g_csum[1];
__device__ int   g_segstart[GNUM + 1];
__device__ float g_m1 [GNUM * OUTD];
__device__ float g_xm1[GNUM * OUTD];
__device__ float g_m2 [GNUM * OUTD];
__device__ float g_xm2[GNUM * FIN];
__device__ float g_bnsum[FIN];
__device__ float g_bnsq [FIN];
__device__ float g_mu  [FIN];
__device__ float g_rstd[FIN];

// ---------------- 128x64-tile SGEMM, double buffered ----------------
// C(N x M) = A(N x K) @ B(K x M)
// EPI: 0 = +bias, 1 = relu(+bias), 2 = relu(+bias - xm[batch[r]]), 3 = +bias - xm[batch[r]]
template<int K, int M, int EPI>
__global__ void __launch_bounds__(256)
gemm128(const float* __restrict__ A, const float* __restrict__ B,
        const float* __restrict__ bias, const float* __restrict__ xm,
        const int* __restrict__ batch, float* __restrict__ C, int Nrows)
{
    constexpr int BK = 16;
    constexpr int NP = K / BK;
    __shared__ float As[2][BK][132];   // [k][m], padded
    __shared__ float Bs[2][BK][68];    // [k][n], padded

    const int tid  = threadIdx.x;          // 256 threads
    const int row0 = blockIdx.x * 128;
    const int col0 = blockIdx.y * 64;

    // A loaders: row ar (0..127), k-offset ak (0 or 8), 8 consecutive floats
    const int ar = tid & 127;
    const int ak = (tid >> 7) * 8;
    const bool arow_ok = (row0 + ar) < Nrows;
    const float* Aptr = A + (size_t)(row0 + ar) * K + ak;

    // B loaders: k row bk (0..15), 4 consecutive cols
    const int bk = tid >> 4;
    const int bn = (tid & 15) * 4;
    const float* Bptr = B + (size_t)bk * M + col0 + bn;

    // compute mapping: 8 rows x 4 cols per thread
    const int ty = tid >> 4;   // 0..15 -> rows ty*8..ty*8+7
    const int tx = tid & 15;   // cols tx*4..tx*4+3

    float acc[8][4];
#pragma unroll
    for (int i = 0; i < 8; i++)
#pragma unroll
        for (int j = 0; j < 4; j++) acc[i][j] = 0.f;

    float4 a0 = make_float4(0.f,0.f,0.f,0.f), a1 = a0, b0;
    if (arow_ok) { a0 = *(const float4*)Aptr; a1 = *(const float4*)(Aptr + 4); }
    b0 = *(const float4*)Bptr;

    int buf = 0;
    As[0][ak+0][ar] = a0.x; As[0][ak+1][ar] = a0.y;
    As[0][ak+2][ar] = a0.z; As[0][ak+3][ar] = a0.w;
    As[0][ak+4][ar] = a1.x; As[0][ak+5][ar] = a1.y;
    As[0][ak+6][ar] = a1.z; As[0][ak+7][ar] = a1.w;
    *(float4*)&Bs[0][bk][bn] = b0;
    __syncthreads();

    for (int p = 0; p < NP; ++p) {
        if (p + 1 < NP) {
            const float* Ap = Aptr + (p + 1) * BK;
            a0 = make_float4(0.f,0.f,0.f,0.f); a1 = a0;
            if (arow_ok) { a0 = *(const float4*)Ap; a1 = *(const float4*)(Ap + 4); }
            b0 = *(const float4*)(Bptr + (size_t)(p + 1) * BK * M);
        }
#pragma unroll
        for (int k = 0; k < BK; ++k) {
            float ra[8], rb[4];
            *(float4*)&ra[0] = *(const float4*)&As[buf][k][ty * 8];
            *(float4*)&ra[4] = *(const float4*)&As[buf][k][ty * 8 + 4];
            *(float4*)&rb[0] = *(const float4*)&Bs[buf][k][tx * 4];
#pragma unroll
            for (int i = 0; i < 8; i++)
#pragma unroll
                for (int j = 0; j < 4; j++) acc[i][j] += ra[i] * rb[j];
        }
        if (p + 1 < NP) {
            buf ^= 1;
            As[buf][ak+0][ar] = a0.x; As[buf][ak+1][ar] = a0.y;
            As[buf][ak+2][ar] = a0.z; As[buf][ak+3][ar] = a0.w;
            As[buf][ak+4][ar] = a1.x; As[buf][ak+5][ar] = a1.y;
            As[buf][ak+6][ar] = a1.z; As[buf][ak+7][ar] = a1.w;
            *(float4*)&Bs[buf][bk][bn] = b0;
            __syncthreads();
        }
    }

    const int rbase = row0 + ty * 8;
    const int cbase = col0 + tx * 4;
#pragma unroll
    for (int i = 0; i < 8; i++) {
        int r = rbase + i;
        if (r >= Nrows) continue;
        int bidx = 0;
        if (EPI >= 2) bidx = batch[r];
#pragma unroll
        for (int j = 0; j < 4; j++) {
            int c = cbase + j;
            float v = acc[i][j];
            if (bias) v += bias[c];
            if (EPI >= 2) v -= xm[bidx * M + c];
            if (EPI == 1 || EPI == 2) v = fmaxf(v, 0.f);
            C[(size_t)r * M + c] = v;
        }
    }
}

// ---------------- Msum[i][j] = sum_h sum_k T_h[i][k] * W_h[j][k] ----------------
__global__ void msum_kernel(const float* __restrict__ W_att)
{
    int idx = blockIdx.x * 256 + threadIdx.x;   // 64 blocks x 256
    int i = idx >> 7, j = idx & 127;
    float s = 0.f;
#pragma unroll 1
    for (int h = 0; h < HEADS; h++) {
        const float* T = g_T + (size_t)h * ATTD * ATTD + i * ATTD;
        const float* W = W_att + (size_t)h * FIN * ATTD + j * ATTD;
#pragma unroll 8
        for (int k = 0; k < ATTD; k++) s += T[k] * W[k];
    }
    g_msum[i * FIN + j] = s;
}

// ---------------- vsum/usum/csum from W, A, b (1 block, 128 threads) -----------
__global__ void vec_kernel(const float* __restrict__ W_att,
                           const float* __restrict__ b_att,
                           const float* __restrict__ A_att)
{
    __shared__ float w1[ATTD], w2[ATTD], sb[ATTD], red[128];
    int t = threadIdx.x;
    float vs = 0.f, us = 0.f, cs = 0.f;
    for (int h = 0; h < HEADS; h++) {
        const float* A = A_att + (size_t)h * ATTD * ATTD;
        const float* W = W_att + (size_t)h * FIN * ATTD;
        sb[t] = b_att[h * ATTD + t];
        __syncthreads();
        float s1 = 0.f, s2 = 0.f;
        for (int j = 0; j < ATTD; j++) {
            s1 += A[t * ATTD + j] * sb[j];
            s2 += A[j * ATTD + t] * sb[j];
        }
        w1[t] = s1; w2[t] = s2;
        cs += sb[t] * s1;
        __syncthreads();
        float a1 = 0.f, a2 = 0.f;
        for (int k = 0; k < ATTD; k++) {
            a1 += W[t * ATTD + k] * w1[k];
            a2 += W[t * ATTD + k] * w2[k];
        }
        vs += a1; us += a2;
        __syncthreads();
    }
    g_vsum[t] = vs; g_usum[t] = us;
    red[t] = cs;
    __syncthreads();
    for (int o = 64; o; o >>= 1) {
        if (t < o) red[t] += red[t + o];
        __syncthreads();
    }
    if (t == 0) g_csum[0] = red[0];
    // also zero BN accumulators here (deterministic per launch)
    if (t < FIN) { g_bnsum[t] = 0.f; g_bnsq[t] = 0.f; }
}

// ---------------- per-node scalar terms: ar = x·vsum + csum, ac = x·usum -------
__global__ void nodescalar_kernel(const float* __restrict__ x, int Nrows)
{
    __shared__ float sv[FIN], su[FIN];
    int tid = threadIdx.x;                  // 256
    if (tid < FIN) { sv[tid] = g_vsum[tid]; su[tid] = g_usum[tid]; }
    __syncthreads();
    int warp = tid >> 5, lane = tid & 31;
    int row = blockIdx.x * 8 + warp;
    if (row >= Nrows) return;
    float4 xv = ((const float4*)(x + (size_t)row * FIN))[lane];
    float4 v4 = ((const float4*)sv)[lane];
    float4 u4 = ((const float4*)su)[lane];
    float s1 = xv.x*v4.x + xv.y*v4.y + xv.z*v4.z + xv.w*v4.w;
    float s2 = xv.x*u4.x + xv.y*u4.y + xv.z*u4.z + xv.w*u4.w;
#pragma unroll
    for (int o = 16; o; o >>= 1) {
        s1 += __shfl_xor_sync(0xffffffffu, s1, o);
        s2 += __shfl_xor_sync(0xffffffffu, s2, o);
    }
    if (lane == 0) { g_ar[row] = s1 + g_csum[0]; g_ac[row] = s2; }
}

// ---------------- single-pass edge score + sigmoid ----------------
__global__ void edge_kernel(const int* __restrict__ ei, const float* __restrict__ x,
                            float* __restrict__ out_att, int E_)
{
    int w = (blockIdx.x * blockDim.x + threadIdx.x) >> 5;
    int lane = threadIdx.x & 31;
    if (w >= E_) return;
    int r = ei[w];
    int c = ei[E_ + w];
    float4 a = ((const float4*)(g_z + (size_t)r * FIN))[lane];
    float4 b = ((const float4*)(x   + (size_t)c * FIN))[lane];
    float s = a.x * b.x + a.y * b.y + a.z * b.z + a.w * b.w;
#pragma unroll
    for (int o = 16; o; o >>= 1) s += __shfl_xor_sync(0xffffffffu, s, o);
    if (lane == 0) {
        float t = s + g_ar[r] + g_ac[c];
        out_att[w] = 1.f / (1.f + expf(-0.25f * t));
    }
}

// ---------------- fused fv + first set_fn layer (warp per row) ----------------
__global__ void filt2_kernel(const float* __restrict__ W_f2, const float* __restrict__ b_f2,
                             const float* __restrict__ W_l0, const float* __restrict__ b_l0,
                             int Nrows)
{
    __shared__ float sW2[HIDDEN * NFILT];
    __shared__ float sWe[NFILT * OUTD];
    __shared__ float sb2[NFILT];
    __shared__ float sbl[OUTD];

    int tid = threadIdx.x; // 256
    for (int i = tid; i < HIDDEN * NFILT; i += 256) sW2[i] = W_f2[i];
    for (int i = tid; i < NFILT * OUTD; i += 256) {
        int p = i / OUTD, c = i % OUTD;
        sWe[i] = W_l0[(2 * p) * OUTD + c] + W_l0[(2 * p + 1) * OUTD + c];
    }
    if (tid < NFILT) sb2[tid] = b_f2[tid];
    if (tid < OUTD)  sbl[tid] = b_l0[tid];
    __syncthreads();

    int warp = tid >> 5, lane = tid & 31;
    int row = blockIdx.x * 8 + warp;
    if (row >= Nrows) return;

    const float* hrow = g_h + (size_t)row * HIDDEN;
    float f[NFILT];
#pragma unroll
    for (int j = 0; j < NFILT; j++) f[j] = 0.f;
#pragma unroll
    for (int kk = 0; kk < HIDDEN / 32; kk++) {
        float hv = hrow[lane + kk * 32];
        const float* wrow = &sW2[(lane + kk * 32) * NFILT];
#pragma unroll
        for (int j = 0; j < NFILT; j++) f[j] += hv * wrow[j];
    }
#pragma unroll
    for (int o = 16; o; o >>= 1)
#pragma unroll
        for (int j = 0; j < NFILT; j++) f[j] += __shfl_xor_sync(0xffffffffu, f[j], o);
#pragma unroll
    for (int j = 0; j < NFILT; j++) f[j] += sb2[j];

    float* orow = g_x0a + (size_t)row * OUTD;
#pragma unroll
    for (int t = 0; t < 2; t++) {
        int c = lane + t * 32;
        float o = sbl[c];
#pragma unroll
        for (int j = 0; j < NFILT; j++) o += f[j] * sWe[j * OUTD + c];
        orow[c] = fmaxf(o, 0.f);
    }
}

// ---------------- segment boundaries (batch sorted) ----------------
__global__ void segbounds_kernel(const int* __restrict__ batch, int Nrows)
{
    int i = blockIdx.x * blockDim.x + threadIdx.x;
    if (i >= Nrows) return;
    int b = batch[i];
    int prev = (i == 0) ? -1 : batch[i - 1];
    for (int g = prev + 1; g <= b; ++g) g_segstart[g] = i;
    if (i == Nrows - 1)
        for (int g = b + 1; g <= GNUM; ++g) g_segstart[g] = Nrows;
}

// ---------------- segment mean (block per graph) ----------------
template<int C>
__global__ void segmean_kernel(const float* __restrict__ X, float* __restrict__ out)
{
    const int T = 256;
    int g = blockIdx.x;
    int s = g_segstart[g], e = g_segstart[g + 1];
    int tid = threadIdx.x;
    int col = tid % C, rgrp = tid / C;
    const int ngrp = T / C;
    float acc = 0.f;
    for (int r = s + rgrp; r < e; r += ngrp) acc += X[(size_t)r * C + col];
    __shared__ float sh[T];
    sh[tid] = acc;
    __syncthreads();
    if (tid < C) {
        float t = 0.f;
#pragma unroll
        for (int k = 0; k < ngrp; k++) t += sh[tid + k * C];
        float cnt = (float)(e - s);
        out[g * C + tid] = t / fmaxf(cnt, 1.f);
    }
}

// ---------------- small GEMM: C(G x M) = A(G x K) @ B(K x M) ----------------
template<int K, int M>
__global__ void small_gemm(const float* __restrict__ A, const float* __restrict__ B,
                           float* __restrict__ C)
{
    int g = blockIdx.x;
    __shared__ float a[K];
    if (threadIdx.x < K) a[threadIdx.x] = A[g * K + threadIdx.x];
    __syncthreads();
    for (int j = threadIdx.x; j < M; j += blockDim.x) {
        float s = 0.f;
#pragma unroll 8
        for (int k = 0; k < K; k++) s += a[k] * B[k * M + j];
        C[g * M + j] = s;
    }
}

// ---------------- BatchNorm stats over relu(g_x0c) ----------------
__global__ void bn_stats_kernel(int Nrows)
{
    int col = threadIdx.x; // 128
    float s = 0.f, q = 0.f;
    for (int r = blockIdx.x; r < Nrows; r += gridDim.x) {
        float v = fmaxf(g_x0c[(size_t)r * FIN + col], 0.f);
        s += v; q += v * v;
    }
    atomicAdd(&g_bnsum[col], s);
    atomicAdd(&g_bnsq[col], q);
}

__global__ void bn_fin_kernel(int Nrows)
{
    int c = threadIdx.x;
    float inv = 1.f / (float)Nrows;
    float mu = g_bnsum[c] * inv;
    float var = g_bnsq[c] * inv - mu * mu;
    g_mu[c] = mu;
    g_rstd[c] = rsqrtf(var + BN_EPS);
}

// ---------------- final: out = x + (relu(x0c)-mu)*rstd*gamma + beta ----------------
__global__ void final_kernel(const float* __restrict__ x, const float* __restrict__ gamma,
                             const float* __restrict__ beta, float* __restrict__ out, int Nrows)
{
    int i = blockIdx.x * blockDim.x + threadIdx.x;
    if (i >= Nrows * FIN) return;
    int c = i & (FIN - 1);
    float h = fmaxf(g_x0c[i], 0.f);
    out[i] = x[i] + (h - g_mu[c]) * g_rstd[c] * gamma[c] + beta[c];
}

// ============================================================================
extern "C" void kernel_launch(void* const* d_in, const int* in_sizes, int n_in,
                              void* d_out, int out_size)
{
    const float* x       = (const float*)d_in[0];
    const int*   ei      = (const int*)  d_in[1];
    const int*   batch   = (const int*)  d_in[2];
    const float* W_f1    = (const float*)d_in[3];
    const float* b_f1    = (const float*)d_in[4];
    const float* W_f2    = (const float*)d_in[5];
    const float* b_f2    = (const float*)d_in[6];
    const float* W_l0    = (const float*)d_in[7];
    const float* b_l0    = (const float*)d_in[8];
    const float* G1      = (const float*)d_in[9];
    const float* b_g1    = (const float*)d_in[10];
    const float* L1      = (const float*)d_in[11];
    const float* G2      = (const float*)d_in[12];
    const float* b_g2    = (const float*)d_in[13];
    const float* L2      = (const float*)d_in[14];
    const float* bn_gamma= (const float*)d_in[15];
    const float* bn_beta = (const float*)d_in[16];
    const float* W_att   = (const float*)d_in[17];
    const float* b_att   = (const float*)d_in[18];
    const float* A_att   = (const float*)d_in[19];

    const int N = in_sizes[0] / FIN;
    const int E = in_sizes[1] / 2;

    float* out_x   = (float*)d_out;
    float* out_att = (float*)d_out + (size_t)N * FIN;

    float* z_p   = nullptr; cudaGetSymbolAddress((void**)&z_p,   g_z);
    float* h_p   = nullptr; cudaGetSymbolAddress((void**)&h_p,   g_h);
    float* x0a_p = nullptr; cudaGetSymbolAddress((void**)&x0a_p, g_x0a);
    float* x0b_p = nullptr; cudaGetSymbolAddress((void**)&x0b_p, g_x0b);
    float* x0c_p = nullptr; cudaGetSymbolAddress((void**)&x0c_p, g_x0c);
    float* T_p   = nullptr; cudaGetSymbolAddress((void**)&T_p,   g_T);
    float* ms_p  = nullptr; cudaGetSymbolAddress((void**)&ms_p,  g_msum);
    float* m1_p  = nullptr; cudaGetSymbolAddress((void**)&m1_p,  g_m1);
    float* xm1_p = nullptr; cudaGetSymbolAddress((void**)&xm1_p, g_xm1);
    float* m2_p  = nullptr; cudaGetSymbolAddress((void**)&m2_p,  g_m2);
    float* xm2_p = nullptr; cudaGetSymbolAddress((void**)&xm2_p, g_xm2);

    const int gemmN = (N + 127) / 128;

    // ---- attention precompute: T_h = W_h @ A_h ; Msum = sum_h T_h @ W_h^T ----
    for (int h = 0; h < HEADS; h++) {
        gemm128<ATTD, ATTD, 0><<<dim3(1, ATTD / 64), 256>>>(
            W_att + (size_t)h * FIN * ATTD, A_att + (size_t)h * ATTD * ATTD,
            nullptr, nullptr, nullptr, T_p + (size_t)h * ATTD * ATTD, FIN);
    }
    msum_kernel<<<FIN * FIN / 256, 256>>>(W_att);
    vec_kernel<<<1, 128>>>(W_att, b_att, A_att);

    // ---- attention main: Z = x @ Msum ; per-node scalars ; edge pass ----
    gemm128<FIN, FIN, 0><<<dim3(gemmN, FIN / 64), 256>>>(
        x, ms_p, nullptr, nullptr, nullptr, z_p, N);
    nodescalar_kernel<<<(N + 7) / 8, 256>>>(x, N);
    edge_kernel<<<(E + 7) / 8, 256>>>(ei, x, out_att, E);

    // ---- filtration MLP ----
    gemm128<FIN, HIDDEN, 1><<<dim3(gemmN, HIDDEN / 64), 256>>>(
        x, W_f1, b_f1, nullptr, nullptr, h_p, N);
    filt2_kernel<<<(N + 7) / 8, 256>>>(W_f2, b_f2, W_l0, b_l0, N);

    // ---- segment structure ----
    segbounds_kernel<<<(N + 255) / 256, 256>>>(batch, N);

    // ---- DeepSet 1 ----
    segmean_kernel<OUTD><<<GNUM, 256>>>(x0a_p, m1_p);
    small_gemm<OUTD, OUTD><<<GNUM, 128>>>(m1_p, L1, xm1_p);
    gemm128<OUTD, OUTD, 2><<<dim3(gemmN, 1), 256>>>(
        x0a_p, G1, b_g1, xm1_p, batch, x0b_p, N);

    // ---- DeepSet 2 ----
    segmean_kernel<OUTD><<<GNUM, 256>>>(x0b_p, m2_p);
    small_gemm<OUTD, FIN><<<GNUM, 128>>>(m2_p, L2, xm2_p);
    gemm128<OUTD, FIN, 3><<<dim3(gemmN, FIN / 64), 256>>>(
        x0b_p, G2, b_g2, xm2_p, batch, x0c_p, N);

    // ---- BatchNorm + residual ----
    bn_stats_kernel<<<512, FIN>>>(N);
    bn_fin_kernel<<<1, FIN>>>(N);
    final_kernel<<<(N * FIN + 255) / 256, 256>>>(x, bn_gamma, bn_beta, out_x, N);
}

// round 11
// speedup vs baseline: 2.0114x; 1.1810x over previous
#include <cuda_runtime.h>
#include <math.h>

// Problem constants (fixed by the dataset)
#define NMAX   100000
#define EMAX   200000
#define GNUM   64
#define FIN    128
#define HIDDEN 256
#define NFILT  8
#define OUTD   64
#define ATTD   128
#define HEADS  4
#define BN_EPS 1e-5f

// ---------------- scratch (static device globals; no allocation) ----------------
__device__ float g_z  [(size_t)NMAX * FIN];    // x @ Msum
__device__ float g_h  [(size_t)NMAX * HIDDEN]; // relu(x@W_f1+b_f1)
__device__ float g_x0a[(size_t)NMAX * OUTD];
__device__ float g_x0b[(size_t)NMAX * OUTD];
__device__ float g_x0c[(size_t)NMAX * FIN];
__device__ float g_ar [NMAX];                  // x·vsum + csum  (row term)
__device__ float g_ac [NMAX];                  // x·usum        (col term)
__device__ float g_T  [HEADS * ATTD * ATTD];   // per-head W@A
__device__ float g_msum[FIN * FIN];            // sum_h W A W^T
__device__ float g_vsum[FIN];
__device__ float g_usum[FIN];
__device__ float g_csum[1];
__device__ int   g_segstart[GNUM + 1];
__device__ float g_xm1[GNUM * OUTD];
__device__ float g_xm2[GNUM * FIN];
__device__ float g_bnsum[FIN];
__device__ float g_bnsq [FIN];

// ================= 128x128-tile SGEMM, 8x8/thread, BK=8, double buffered ======
// C(N x Cld slice) = A(N x K) @ B(K x Bld slice)
// EPI: 0 = +bias, 1 = relu(+bias), 2 = relu(+bias - xm[batch[r]]), 3 = +bias - xm[batch[r]]
// MULTI: blockIdx.z selects head: A += z*128*K, B += z*K*Bld, C += z*128*Cld
// STATS: accumulate sum/sumsq of relu(value) into g_bnsum/g_bnsq (per column)
template<int K, int EPI, bool MULTI, bool STATS>
__global__ void __launch_bounds__(256, 2)
gemm_big(const float* __restrict__ A, const float* __restrict__ B,
         const float* __restrict__ bias, const float* __restrict__ xm,
         const int* __restrict__ batch, float* __restrict__ C,
         int Nrows, int Bld, int Cld)
{
    constexpr int BK = 8;
    constexpr int NP = K / BK;
    __shared__ float As[2][BK][132];
    __shared__ float Bs[2][BK][132];
    __shared__ float ssum[128];
    __shared__ float ssq [128];

    const int tid  = threadIdx.x;          // 256 threads
    const int row0 = blockIdx.x * 128;
    const int col0 = blockIdx.y * 128;

    if (MULTI) {
        size_t z = blockIdx.z;
        A += z * 128 * K;
        B += z * (size_t)K * Bld;
        C += z * 128 * Cld;
    }
    if (STATS && tid < 128) { ssum[tid] = 0.f; ssq[tid] = 0.f; }

    // A loader: one float4/thread: row ar (0..127), k offset ak (0 or 4)
    const int ar = tid >> 1;
    const int ak = (tid & 1) * 4;
    const bool arow_ok = (row0 + ar) < Nrows;
    const float* Aptr = A + (size_t)(row0 + ar) * K + ak;

    // B loader: one float4/thread: k row bk (0..7), 4 cols at bn
    const int bk = tid >> 5;
    const int bn = (tid & 31) * 4;
    const float* Bptr = B + (size_t)bk * Bld + col0 + bn;

    // compute mapping: rows ty*8..+7 ; cols tx*4..+3 and 64+tx*4..+3
    const int ty = tid >> 4;   // 0..15
    const int tx = tid & 15;   // 0..15

    float acc[8][8];
#pragma unroll
    for (int i = 0; i < 8; i++)
#pragma unroll
        for (int j = 0; j < 8; j++) acc[i][j] = 0.f;

    float4 a0 = make_float4(0.f,0.f,0.f,0.f), b0;
    if (arow_ok) a0 = *(const float4*)Aptr;
    b0 = *(const float4*)Bptr;

    int buf = 0;
    As[0][ak+0][ar] = a0.x; As[0][ak+1][ar] = a0.y;
    As[0][ak+2][ar] = a0.z; As[0][ak+3][ar] = a0.w;
    *(float4*)&Bs[0][bk][bn] = b0;
    __syncthreads();

    for (int p = 0; p < NP; ++p) {
        if (p + 1 < NP) {
            a0 = make_float4(0.f,0.f,0.f,0.f);
            if (arow_ok) a0 = *(const float4*)(Aptr + (p + 1) * BK);
            b0 = *(const float4*)(Bptr + (size_t)(p + 1) * BK * Bld);
        }
#pragma unroll
        for (int k = 0; k < BK; ++k) {
            float ra[8], rb[8];
            *(float4*)&ra[0] = *(const float4*)&As[buf][k][ty * 8];
            *(float4*)&ra[4] = *(const float4*)&As[buf][k][ty * 8 + 4];
            *(float4*)&rb[0] = *(const float4*)&Bs[buf][k][tx * 4];
            *(float4*)&rb[4] = *(const float4*)&Bs[buf][k][64 + tx * 4];
#pragma unroll
            for (int i = 0; i < 8; i++)
#pragma unroll
                for (int j = 0; j < 8; j++) acc[i][j] += ra[i] * rb[j];
        }
        if (p + 1 < NP) {
            buf ^= 1;
            As[buf][ak+0][ar] = a0.x; As[buf][ak+1][ar] = a0.y;
            As[buf][ak+2][ar] = a0.z; As[buf][ak+3][ar] = a0.w;
            *(float4*)&Bs[buf][bk][bn] = b0;
            __syncthreads();
        }
    }

    // epilogue
    float cs[8], cq[8];
    if (STATS) {
#pragma unroll
        for (int j = 0; j < 8; j++) { cs[j] = 0.f; cq[j] = 0.f; }
    }
    const int rbase = row0 + ty * 8;
#pragma unroll
    for (int i = 0; i < 8; i++) {
        int r = rbase + i;
        if (r >= Nrows) continue;
        int bidx = 0;
        if (EPI >= 2) bidx = batch[r];
        float v[8];
#pragma unroll
        for (int j = 0; j < 8; j++) {
            int c = col0 + ((j < 4) ? (tx * 4 + j) : (64 + tx * 4 + j - 4));
            float t = acc[i][j];
            if (bias) t += bias[c];
            if (EPI >= 2) t -= xm[bidx * Cld + c];
            if (EPI == 1 || EPI == 2) t = fmaxf(t, 0.f);
            v[j] = t;
            if (STATS) {
                float rv = fmaxf(t, 0.f);
                cs[j] += rv; cq[j] += rv * rv;
            }
        }
        float* Crow = C + (size_t)r * Cld + col0;
        *(float4*)&Crow[tx * 4]      = make_float4(v[0], v[1], v[2], v[3]);
        *(float4*)&Crow[64 + tx * 4] = make_float4(v[4], v[5], v[6], v[7]);
    }
    if (STATS) {
#pragma unroll
        for (int j = 0; j < 8; j++) {
            int ct = (j < 4) ? (tx * 4 + j) : (64 + tx * 4 + j - 4);
            atomicAdd(&ssum[ct], cs[j]);
            atomicAdd(&ssq[ct],  cq[j]);
        }
        __syncthreads();
        if (tid < 128) {
            atomicAdd(&g_bnsum[col0 + tid], ssum[tid]);
            atomicAdd(&g_bnsq [col0 + tid], ssq[tid]);
        }
    }
}

// ---------------- 128x64-tile SGEMM (for M=64 DeepSet1), BK=16 ----------------
template<int K, int M, int EPI>
__global__ void __launch_bounds__(256)
gemm128(const float* __restrict__ A, const float* __restrict__ B,
        const float* __restrict__ bias, const float* __restrict__ xm,
        const int* __restrict__ batch, float* __restrict__ C, int Nrows)
{
    constexpr int BK = 16;
    constexpr int NP = K / BK;
    __shared__ float As[2][BK][132];
    __shared__ float Bs[2][BK][68];

    const int tid  = threadIdx.x;
    const int row0 = blockIdx.x * 128;
    const int col0 = blockIdx.y * 64;

    const int ar = tid & 127;
    const int ak = (tid >> 7) * 8;
    const bool arow_ok = (row0 + ar) < Nrows;
    const float* Aptr = A + (size_t)(row0 + ar) * K + ak;

    const int bk = tid >> 4;
    const int bn = (tid & 15) * 4;
    const float* Bptr = B + (size_t)bk * M + col0 + bn;

    const int ty = tid >> 4;
    const int tx = tid & 15;

    float acc[8][4];
#pragma unroll
    for (int i = 0; i < 8; i++)
#pragma unroll
        for (int j = 0; j < 4; j++) acc[i][j] = 0.f;

    float4 a0 = make_float4(0.f,0.f,0.f,0.f), a1 = a0, b0;
    if (arow_ok) { a0 = *(const float4*)Aptr; a1 = *(const float4*)(Aptr + 4); }
    b0 = *(const float4*)Bptr;

    int buf = 0;
    As[0][ak+0][ar] = a0.x; As[0][ak+1][ar] = a0.y;
    As[0][ak+2][ar] = a0.z; As[0][ak+3][ar] = a0.w;
    As[0][ak+4][ar] = a1.x; As[0][ak+5][ar] = a1.y;
    As[0][ak+6][ar] = a1.z; As[0][ak+7][ar] = a1.w;
    *(float4*)&Bs[0][bk][bn] = b0;
    __syncthreads();

    for (int p = 0; p < NP; ++p) {
        if (p + 1 < NP) {
            const float* Ap = Aptr + (p + 1) * BK;
            a0 = make_float4(0.f,0.f,0.f,0.f); a1 = a0;
            if (arow_ok) { a0 = *(const float4*)Ap; a1 = *(const float4*)(Ap + 4); }
            b0 = *(const float4*)(Bptr + (size_t)(p + 1) * BK * M);
        }
#pragma unroll
        for (int k = 0; k < BK; ++k) {
            float ra[8], rb[4];
            *(float4*)&ra[0] = *(const float4*)&As[buf][k][ty * 8];
            *(float4*)&ra[4] = *(const float4*)&As[buf][k][ty * 8 + 4];
            *(float4*)&rb[0] = *(const float4*)&Bs[buf][k][tx * 4];
#pragma unroll
            for (int i = 0; i < 8; i++)
#pragma unroll
                for (int j = 0; j < 4; j++) acc[i][j] += ra[i] * rb[j];
        }
        if (p + 1 < NP) {
            buf ^= 1;
            As[buf][ak+0][ar] = a0.x; As[buf][ak+1][ar] = a0.y;
            As[buf][ak+2][ar] = a0.z; As[buf][ak+3][ar] = a0.w;
            As[buf][ak+4][ar] = a1.x; As[buf][ak+5][ar] = a1.y;
            As[buf][ak+6][ar] = a1.z; As[buf][ak+7][ar] = a1.w;
            *(float4*)&Bs[buf][bk][bn] = b0;
            __syncthreads();
        }
    }

    const int rbase = row0 + ty * 8;
    const int cbase = col0 + tx * 4;
#pragma unroll
    for (int i = 0; i < 8; i++) {
        int r = rbase + i;
        if (r >= Nrows) continue;
        int bidx = 0;
        if (EPI >= 2) bidx = batch[r];
#pragma unroll
        for (int j = 0; j < 4; j++) {
            int c = cbase + j;
            float v = acc[i][j];
            if (bias) v += bias[c];
            if (EPI >= 2) v -= xm[bidx * M + c];
            if (EPI == 1 || EPI == 2) v = fmaxf(v, 0.f);
            C[(size_t)r * M + c] = v;
        }
    }
}

// ---------------- Msum[i][j] = sum_h sum_k T_h[i][k] * W_h[j][k] ----------------
__global__ void msum_kernel(const float* __restrict__ W_att)
{
    int idx = blockIdx.x * 256 + threadIdx.x;
    int i = idx >> 7, j = idx & 127;
    float s = 0.f;
#pragma unroll 1
    for (int h = 0; h < HEADS; h++) {
        const float* T = g_T + (size_t)h * ATTD * ATTD + i * ATTD;
        const float* W = W_att + (size_t)h * FIN * ATTD + j * ATTD;
#pragma unroll 8
        for (int k = 0; k < ATTD; k++) s += T[k] * W[k];
    }
    g_msum[i * FIN + j] = s;
}

// ---------------- vsum/usum/csum from W, A, b (1 block, 128 threads) -----------
__global__ void vec_kernel(const float* __restrict__ W_att,
                           const float* __restrict__ b_att,
                           const float* __restrict__ A_att)
{
    __shared__ float w1[ATTD], w2[ATTD], sb[ATTD], red[128];
    int t = threadIdx.x;
    float vs = 0.f, us = 0.f, cs = 0.f;
    for (int h = 0; h < HEADS; h++) {
        const float* A = A_att + (size_t)h * ATTD * ATTD;
        const float* W = W_att + (size_t)h * FIN * ATTD;
        sb[t] = b_att[h * ATTD + t];
        __syncthreads();
        float s1 = 0.f, s2 = 0.f;
        for (int j = 0; j < ATTD; j++) {
            s1 += A[t * ATTD + j] * sb[j];
            s2 += A[j * ATTD + t] * sb[j];
        }
        w1[t] = s1; w2[t] = s2;
        cs += sb[t] * s1;
        __syncthreads();
        float a1 = 0.f, a2 = 0.f;
        for (int k = 0; k < ATTD; k++) {
            a1 += W[t * ATTD + k] * w1[k];
            a2 += W[t * ATTD + k] * w2[k];
        }
        vs += a1; us += a2;
        __syncthreads();
    }
    g_vsum[t] = vs; g_usum[t] = us;
    red[t] = cs;
    __syncthreads();
    for (int o = 64; o; o >>= 1) {
        if (t < o) red[t] += red[t + o];
        __syncthreads();
    }
    if (t == 0) g_csum[0] = red[0];
    // zero BN accumulators (deterministic per launch)
    if (t < FIN) { g_bnsum[t] = 0.f; g_bnsq[t] = 0.f; }
}

// ---------------- per-node scalar terms: ar = x·vsum + csum, ac = x·usum -------
__global__ void nodescalar_kernel(const float* __restrict__ x, int Nrows)
{
    __shared__ float sv[FIN], su[FIN];
    int tid = threadIdx.x;                  // 256
    if (tid < FIN) { sv[tid] = g_vsum[tid]; su[tid] = g_usum[tid]; }
    __syncthreads();
    int warp = tid >> 5, lane = tid & 31;
    int row = blockIdx.x * 8 + warp;
    if (row >= Nrows) return;
    float4 xv = ((const float4*)(x + (size_t)row * FIN))[lane];
    float4 v4 = ((const float4*)sv)[lane];
    float4 u4 = ((const float4*)su)[lane];
    float s1 = xv.x*v4.x + xv.y*v4.y + xv.z*v4.z + xv.w*v4.w;
    float s2 = xv.x*u4.x + xv.y*u4.y + xv.z*u4.z + xv.w*u4.w;
#pragma unroll
    for (int o = 16; o; o >>= 1) {
        s1 += __shfl_xor_sync(0xffffffffu, s1, o);
        s2 += __shfl_xor_sync(0xffffffffu, s2, o);
    }
    if (lane == 0) { g_ar[row] = s1 + g_csum[0]; g_ac[row] = s2; }
}

// ---------------- single-pass edge score + sigmoid ----------------
__global__ void edge_kernel(const int* __restrict__ ei, const float* __restrict__ x,
                            float* __restrict__ out_att, int E_)
{
    int w = (blockIdx.x * blockDim.x + threadIdx.x) >> 5;
    int lane = threadIdx.x & 31;
    if (w >= E_) return;
    int r = ei[w];
    int c = ei[E_ + w];
    float4 a = ((const float4*)(g_z + (size_t)r * FIN))[lane];
    float4 b = ((const float4*)(x   + (size_t)c * FIN))[lane];
    float s = a.x * b.x + a.y * b.y + a.z * b.z + a.w * b.w;
#pragma unroll
    for (int o = 16; o; o >>= 1) s += __shfl_xor_sync(0xffffffffu, s, o);
    if (lane == 0) {
        float t = s + g_ar[r] + g_ac[c];
        out_att[w] = 1.f / (1.f + expf(-0.25f * t));
    }
}

// ---------------- fused fv + first set_fn layer (warp per row) ----------------
__global__ void filt2_kernel(const float* __restrict__ W_f2, const float* __restrict__ b_f2,
                             const float* __restrict__ W_l0, const float* __restrict__ b_l0,
                             int Nrows)
{
    __shared__ float sW2[HIDDEN * NFILT];
    __shared__ float sWe[NFILT * OUTD];
    __shared__ float sb2[NFILT];
    __shared__ float sbl[OUTD];

    int tid = threadIdx.x; // 256
    for (int i = tid; i < HIDDEN * NFILT; i += 256) sW2[i] = W_f2[i];
    for (int i = tid; i < NFILT * OUTD; i += 256) {
        int p = i / OUTD, c = i % OUTD;
        sWe[i] = W_l0[(2 * p) * OUTD + c] + W_l0[(2 * p + 1) * OUTD + c];
    }
    if (tid < NFILT) sb2[tid] = b_f2[tid];
    if (tid < OUTD)  sbl[tid] = b_l0[tid];
    __syncthreads();

    int warp = tid >> 5, lane = tid & 31;
    int row = blockIdx.x * 8 + warp;
    if (row >= Nrows) return;

    const float* hrow = g_h + (size_t)row * HIDDEN;
    float f[NFILT];
#pragma unroll
    for (int j = 0; j < NFILT; j++) f[j] = 0.f;
#pragma unroll
    for (int kk = 0; kk < HIDDEN / 32; kk++) {
        float hv = hrow[lane + kk * 32];
        const float* wrow = &sW2[(lane + kk * 32) * NFILT];
#pragma unroll
        for (int j = 0; j < NFILT; j++) f[j] += hv * wrow[j];
    }
#pragma unroll
    for (int o = 16; o; o >>= 1)
#pragma unroll
        for (int j = 0; j < NFILT; j++) f[j] += __shfl_xor_sync(0xffffffffu, f[j], o);
#pragma unroll
    for (int j = 0; j < NFILT; j++) f[j] += sb2[j];

    float* orow = g_x0a + (size_t)row * OUTD;
#pragma unroll
    for (int t = 0; t < 2; t++) {
        int c = lane + t * 32;
        float o = sbl[c];
#pragma unroll
        for (int j = 0; j < NFILT; j++) o += f[j] * sWe[j * OUTD + c];
        orow[c] = fmaxf(o, 0.f);
    }
}

// ---------------- segment boundaries (batch sorted) ----------------
__global__ void segbounds_kernel(const int* __restrict__ batch, int Nrows)
{
    int i = blockIdx.x * blockDim.x + threadIdx.x;
    if (i >= Nrows) return;
    int b = batch[i];
    int prev = (i == 0) ? -1 : batch[i - 1];
    for (int g = prev + 1; g <= b; ++g) g_segstart[g] = i;
    if (i == Nrows - 1)
        for (int g = b + 1; g <= GNUM; ++g) g_segstart[g] = Nrows;
}

// ---------------- fused segment mean + (mean @ L): xm (G x M) ----------------
template<int C, int M>
__global__ void segmeanL_kernel(const float* __restrict__ X, const float* __restrict__ L,
                                float* __restrict__ xm)
{
    const int T = 256;
    int g = blockIdx.x;
    int s = g_segstart[g], e = g_segstart[g + 1];
    int tid = threadIdx.x;
    int col = tid % C, rgrp = tid / C;
    const int ngrp = T / C;
    float acc = 0.f;
    for (int r = s + rgrp; r < e; r += ngrp) acc += X[(size_t)r * C + col];
    __shared__ float sh[T];
    __shared__ float smean[C];
    sh[tid] = acc;
    __syncthreads();
    if (tid < C) {
        float t = 0.f;
#pragma unroll
        for (int k = 0; k < ngrp; k++) t += sh[tid + k * C];
        smean[tid] = t / fmaxf((float)(e - s), 1.f);
    }
    __syncthreads();
    for (int j = tid; j < M; j += T) {
        float sm = 0.f;
#pragma unroll 8
        for (int k = 0; k < C; k++) sm += smean[k] * L[k * M + j];
        xm[g * M + j] = sm;
    }
}

// -------- final: out = x + (relu(x0c)-mu)*rstd*gamma + beta (mu/rstd in-block) --
__global__ void final_kernel(const float* __restrict__ x, const float* __restrict__ gamma,
                             const float* __restrict__ beta, float* __restrict__ out,
                             int Nrows)
{
    __shared__ float smu[FIN], srs[FIN], sg[FIN], sbt[FIN];
    int t = threadIdx.x; // 256
    if (t < FIN) {
        float inv = 1.f / (float)Nrows;
        float m = g_bnsum[t] * inv;
        float v = g_bnsq[t] * inv - m * m;
        smu[t] = m;
        srs[t] = rsqrtf(v + BN_EPS);
        sg[t] = gamma[t];
        sbt[t] = beta[t];
    }
    __syncthreads();
    int total = Nrows * FIN;
    for (int i = blockIdx.x * 256 + t; i < total; i += gridDim.x * 256) {
        int c = i & (FIN - 1);
        float h = fmaxf(g_x0c[i], 0.f);
        out[i] = x[i] + (h - smu[c]) * srs[c] * sg[c] + sbt[c];
    }
}

// ============================================================================
extern "C" void kernel_launch(void* const* d_in, const int* in_sizes, int n_in,
                              void* d_out, int out_size)
{
    const float* x       = (const float*)d_in[0];
    const int*   ei      = (const int*)  d_in[1];
    const int*   batch   = (const int*)  d_in[2];
    const float* W_f1    = (const float*)d_in[3];
    const float* b_f1    = (const float*)d_in[4];
    const float* W_f2    = (const float*)d_in[5];
    const float* b_f2    = (const float*)d_in[6];
    const float* W_l0    = (const float*)d_in[7];
    const float* b_l0    = (const float*)d_in[8];
    const float* G1      = (const float*)d_in[9];
    const float* b_g1    = (const float*)d_in[10];
    const float* L1      = (const float*)d_in[11];
    const float* G2      = (const float*)d_in[12];
    const float* b_g2    = (const float*)d_in[13];
    const float* L2      = (const float*)d_in[14];
    const float* bn_gamma= (const float*)d_in[15];
    const float* bn_beta = (const float*)d_in[16];
    const float* W_att   = (const float*)d_in[17];
    const float* b_att   = (const float*)d_in[18];
    const float* A_att   = (const float*)d_in[19];

    const int N = in_sizes[0] / FIN;
    const int E = in_sizes[1] / 2;

    float* out_x   = (float*)d_out;
    float* out_att = (float*)d_out + (size_t)N * FIN;

    float* z_p   = nullptr; cudaGetSymbolAddress((void**)&z_p,   g_z);
    float* h_p   = nullptr; cudaGetSymbolAddress((void**)&h_p,   g_h);
    float* x0a_p = nullptr; cudaGetSymbolAddress((void**)&x0a_p, g_x0a);
    float* x0b_p = nullptr; cudaGetSymbolAddress((void**)&x0b_p, g_x0b);
    float* x0c_p = nullptr; cudaGetSymbolAddress((void**)&x0c_p, g_x0c);
    float* T_p   = nullptr; cudaGetSymbolAddress((void**)&T_p,   g_T);
    float* ms_p  = nullptr; cudaGetSymbolAddress((void**)&ms_p,  g_msum);
    float* xm1_p = nullptr; cudaGetSymbolAddress((void**)&xm1_p, g_xm1);
    float* xm2_p = nullptr; cudaGetSymbolAddress((void**)&xm2_p, g_xm2);

    const int gN = (N + 127) / 128;

    // ---- attention precompute: T_h = W_h @ A_h for ALL heads in one launch ----
    gemm_big<ATTD, 0, true, false><<<dim3(1, 1, HEADS), 256>>>(
        W_att, A_att, nullptr, nullptr, nullptr, T_p, 128, ATTD, ATTD);
    msum_kernel<<<FIN * FIN / 256, 256>>>(W_att);
    vec_kernel<<<1, 128>>>(W_att, b_att, A_att);

    // ---- attention main: Z = x @ Msum ; per-node scalars ; edge pass ----
    gemm_big<FIN, 0, false, false><<<dim3(gN, 1), 256>>>(
        x, ms_p, nullptr, nullptr, nullptr, z_p, N, FIN, FIN);
    nodescalar_kernel<<<(N + 7) / 8, 256>>>(x, N);
    edge_kernel<<<(E + 7) / 8, 256>>>(ei, x, out_att, E);

    // ---- filtration MLP ----
    gemm_big<FIN, 1, false, false><<<dim3(gN, HIDDEN / 128), 256>>>(
        x, W_f1, b_f1, nullptr, nullptr, h_p, N, HIDDEN, HIDDEN);
    filt2_kernel<<<(N + 7) / 8, 256>>>(W_f2, b_f2, W_l0, b_l0, N);

    // ---- segment structure ----
    segbounds_kernel<<<(N + 255) / 256, 256>>>(batch, N);

    // ---- DeepSet 1 ----
    segmeanL_kernel<OUTD, OUTD><<<GNUM, 256>>>(x0a_p, L1, xm1_p);
    gemm128<OUTD, OUTD, 2><<<dim3(gN, 1), 256>>>(
        x0a_p, G1, b_g1, xm1_p, batch, x0b_p, N);

    // ---- DeepSet 2 (stats fused into epilogue) ----
    segmeanL_kernel<OUTD, FIN><<<GNUM, 256>>>(x0b_p, L2, xm2_p);
    gemm_big<OUTD, 3, false, true><<<dim3(gN, 1), 256>>>(
        x0b_p, G2, b_g2, xm2_p, batch, x0c_p, N, FIN, FIN);

    // ---- BatchNorm + residual ----
    final_kernel<<<1024, 256>>>(x, bn_gamma, bn_beta, out_x, N);
}

// round 12
// speedup vs baseline: 2.1931x; 1.0903x over previous
#include <cuda_runtime.h>
#include <cuda_bf16.h>
#include <math.h>

// Problem constants (fixed by the dataset)
#define NMAX   100000
#define EMAX   200000
#define GNUM   64
#define FIN    128
#define HIDDEN 256
#define NFILT  8
#define OUTD   64
#define ATTD   128
#define HEADS  4
#define BN_EPS 1e-5f

// ---------------- scratch (static device globals; no allocation) ----------------
__device__ float g_z  [(size_t)NMAX * FIN];    // x @ Msum
__device__ float g_h  [(size_t)NMAX * HIDDEN]; // relu(x@W_f1+b_f1)
__device__ float g_x0a[(size_t)NMAX * OUTD];
__device__ float g_x0b[(size_t)NMAX * OUTD];
__device__ float g_x0c[(size_t)NMAX * FIN];
__device__ float g_ar [NMAX];                  // x·vsum + csum  (row term)
__device__ float g_ac [NMAX];                  // x·usum        (col term)
__device__ float g_T  [HEADS * ATTD * ATTD];   // per-head W@A
__device__ float g_msum[FIN * FIN];            // sum_h W A W^T
__device__ float g_vsum[FIN];
__device__ float g_usum[FIN];
__device__ float g_csum[1];
__device__ int   g_segstart[GNUM + 1];
__device__ float g_xm1[GNUM * OUTD];
__device__ float g_xm2[GNUM * FIN];
__device__ float g_bnsum[FIN];
__device__ float g_bnsq [FIN];
// bf16 split-precision operands for the fused big GEMM
__device__ __nv_bfloat16 g_A3 [(size_t)NMAX * 384];   // [x_hi | x_lo | x_hi]
__device__ __nv_bfloat16 g_B3t[(size_t)384 * 384];    // n-major: B3t[n][k']

// ================= 128x128-tile SGEMM (kept for precompute + DS2) =============
template<int K, int EPI, bool MULTI, bool STATS>
__global__ void __launch_bounds__(256, 2)
gemm_big(const float* __restrict__ A, const float* __restrict__ B,
         const float* __restrict__ bias, const float* __restrict__ xm,
         const int* __restrict__ batch, float* __restrict__ C,
         int Nrows, int Bld, int Cld)
{
    constexpr int BK = 8;
    constexpr int NP = K / BK;
    __shared__ float As[2][BK][132];
    __shared__ float Bs[2][BK][132];
    __shared__ float ssum[128];
    __shared__ float ssq [128];

    const int tid  = threadIdx.x;
    const int row0 = blockIdx.x * 128;
    const int col0 = blockIdx.y * 128;

    if (MULTI) {
        size_t z = blockIdx.z;
        A += z * 128 * K;
        B += z * (size_t)K * Bld;
        C += z * 128 * Cld;
    }
    if (STATS && tid < 128) { ssum[tid] = 0.f; ssq[tid] = 0.f; }

    const int ar = tid >> 1;
    const int ak = (tid & 1) * 4;
    const bool arow_ok = (row0 + ar) < Nrows;
    const float* Aptr = A + (size_t)(row0 + ar) * K + ak;

    const int bk = tid >> 5;
    const int bn = (tid & 31) * 4;
    const float* Bptr = B + (size_t)bk * Bld + col0 + bn;

    const int ty = tid >> 4;
    const int tx = tid & 15;

    float acc[8][8];
#pragma unroll
    for (int i = 0; i < 8; i++)
#pragma unroll
        for (int j = 0; j < 8; j++) acc[i][j] = 0.f;

    float4 a0 = make_float4(0.f,0.f,0.f,0.f), b0;
    if (arow_ok) a0 = *(const float4*)Aptr;
    b0 = *(const float4*)Bptr;

    int buf = 0;
    As[0][ak+0][ar] = a0.x; As[0][ak+1][ar] = a0.y;
    As[0][ak+2][ar] = a0.z; As[0][ak+3][ar] = a0.w;
    *(float4*)&Bs[0][bk][bn] = b0;
    __syncthreads();

    for (int p = 0; p < NP; ++p) {
        if (p + 1 < NP) {
            a0 = make_float4(0.f,0.f,0.f,0.f);
            if (arow_ok) a0 = *(const float4*)(Aptr + (p + 1) * BK);
            b0 = *(const float4*)(Bptr + (size_t)(p + 1) * BK * Bld);
        }
#pragma unroll
        for (int k = 0; k < BK; ++k) {
            float ra[8], rb[8];
            *(float4*)&ra[0] = *(const float4*)&As[buf][k][ty * 8];
            *(float4*)&ra[4] = *(const float4*)&As[buf][k][ty * 8 + 4];
            *(float4*)&rb[0] = *(const float4*)&Bs[buf][k][tx * 4];
            *(float4*)&rb[4] = *(const float4*)&Bs[buf][k][64 + tx * 4];
#pragma unroll
            for (int i = 0; i < 8; i++)
#pragma unroll
                for (int j = 0; j < 8; j++) acc[i][j] += ra[i] * rb[j];
        }
        if (p + 1 < NP) {
            buf ^= 1;
            As[buf][ak+0][ar] = a0.x; As[buf][ak+1][ar] = a0.y;
            As[buf][ak+2][ar] = a0.z; As[buf][ak+3][ar] = a0.w;
            *(float4*)&Bs[buf][bk][bn] = b0;
            __syncthreads();
        }
    }

    float cs[8], cq[8];
    if (STATS) {
#pragma unroll
        for (int j = 0; j < 8; j++) { cs[j] = 0.f; cq[j] = 0.f; }
    }
    const int rbase = row0 + ty * 8;
#pragma unroll
    for (int i = 0; i < 8; i++) {
        int r = rbase + i;
        if (r >= Nrows) continue;
        int bidx = 0;
        if (EPI >= 2) bidx = batch[r];
        float v[8];
#pragma unroll
        for (int j = 0; j < 8; j++) {
            int c = col0 + ((j < 4) ? (tx * 4 + j) : (64 + tx * 4 + j - 4));
            float t = acc[i][j];
            if (bias) t += bias[c];
            if (EPI >= 2) t -= xm[bidx * Cld + c];
            if (EPI == 1 || EPI == 2) t = fmaxf(t, 0.f);
            v[j] = t;
            if (STATS) {
                float rv = fmaxf(t, 0.f);
                cs[j] += rv; cq[j] += rv * rv;
            }
        }
        float* Crow = C + (size_t)r * Cld + col0;
        *(float4*)&Crow[tx * 4]      = make_float4(v[0], v[1], v[2], v[3]);
        *(float4*)&Crow[64 + tx * 4] = make_float4(v[4], v[5], v[6], v[7]);
    }
    if (STATS) {
#pragma unroll
        for (int j = 0; j < 8; j++) {
            int ct = (j < 4) ? (tx * 4 + j) : (64 + tx * 4 + j - 4);
            atomicAdd(&ssum[ct], cs[j]);
            atomicAdd(&ssq[ct],  cq[j]);
        }
        __syncthreads();
        if (tid < 128) {
            atomicAdd(&g_bnsum[col0 + tid], ssum[tid]);
            atomicAdd(&g_bnsq [col0 + tid], ssq[tid]);
        }
    }
}

// ---------------- 128x64-tile SGEMM (DeepSet1), BK=16 ----------------
template<int K, int M, int EPI>
__global__ void __launch_bounds__(256)
gemm128(const float* __restrict__ A, const float* __restrict__ B,
        const float* __restrict__ bias, const float* __restrict__ xm,
        const int* __restrict__ batch, float* __restrict__ C, int Nrows)
{
    constexpr int BK = 16;
    constexpr int NP = K / BK;
    __shared__ float As[2][BK][132];
    __shared__ float Bs[2][BK][68];

    const int tid  = threadIdx.x;
    const int row0 = blockIdx.x * 128;
    const int col0 = blockIdx.y * 64;

    const int ar = tid & 127;
    const int ak = (tid >> 7) * 8;
    const bool arow_ok = (row0 + ar) < Nrows;
    const float* Aptr = A + (size_t)(row0 + ar) * K + ak;

    const int bk = tid >> 4;
    const int bn = (tid & 15) * 4;
    const float* Bptr = B + (size_t)bk * M + col0 + bn;

    const int ty = tid >> 4;
    const int tx = tid & 15;

    float acc[8][4];
#pragma unroll
    for (int i = 0; i < 8; i++)
#pragma unroll
        for (int j = 0; j < 4; j++) acc[i][j] = 0.f;

    float4 a0 = make_float4(0.f,0.f,0.f,0.f), a1 = a0, b0;
    if (arow_ok) { a0 = *(const float4*)Aptr; a1 = *(const float4*)(Aptr + 4); }
    b0 = *(const float4*)Bptr;

    int buf = 0;
    As[0][ak+0][ar] = a0.x; As[0][ak+1][ar] = a0.y;
    As[0][ak+2][ar] = a0.z; As[0][ak+3][ar] = a0.w;
    As[0][ak+4][ar] = a1.x; As[0][ak+5][ar] = a1.y;
    As[0][ak+6][ar] = a1.z; As[0][ak+7][ar] = a1.w;
    *(float4*)&Bs[0][bk][bn] = b0;
    __syncthreads();

    for (int p = 0; p < NP; ++p) {
        if (p + 1 < NP) {
            const float* Ap = Aptr + (p + 1) * BK;
            a0 = make_float4(0.f,0.f,0.f,0.f); a1 = a0;
            if (arow_ok) { a0 = *(const float4*)Ap; a1 = *(const float4*)(Ap + 4); }
            b0 = *(const float4*)(Bptr + (size_t)(p + 1) * BK * M);
        }
#pragma unroll
        for (int k = 0; k < BK; ++k) {
            float ra[8], rb[4];
            *(float4*)&ra[0] = *(const float4*)&As[buf][k][ty * 8];
            *(float4*)&ra[4] = *(const float4*)&As[buf][k][ty * 8 + 4];
            *(float4*)&rb[0] = *(const float4*)&Bs[buf][k][tx * 4];
#pragma unroll
            for (int i = 0; i < 8; i++)
#pragma unroll
                for (int j = 0; j < 4; j++) acc[i][j] += ra[i] * rb[j];
        }
        if (p + 1 < NP) {
            buf ^= 1;
            As[buf][ak+0][ar] = a0.x; As[buf][ak+1][ar] = a0.y;
            As[buf][ak+2][ar] = a0.z; As[buf][ak+3][ar] = a0.w;
            As[buf][ak+4][ar] = a1.x; As[buf][ak+5][ar] = a1.y;
            As[buf][ak+6][ar] = a1.z; As[buf][ak+7][ar] = a1.w;
            *(float4*)&Bs[buf][bk][bn] = b0;
            __syncthreads();
        }
    }

    const int rbase = row0 + ty * 8;
    const int cbase = col0 + tx * 4;
#pragma unroll
    for (int i = 0; i < 8; i++) {
        int r = rbase + i;
        if (r >= Nrows) continue;
        int bidx = 0;
        if (EPI >= 2) bidx = batch[r];
#pragma unroll
        for (int j = 0; j < 4; j++) {
            int c = cbase + j;
            float v = acc[i][j];
            if (bias) v += bias[c];
            if (EPI >= 2) v -= xm[bidx * M + c];
            if (EPI == 1 || EPI == 2) v = fmaxf(v, 0.f);
            C[(size_t)r * M + c] = v;
        }
    }
}

// ---------------- Msum[i][j] = sum_h sum_k T_h[i][k] * W_h[j][k] ----------------
__global__ void msum_kernel(const float* __restrict__ W_att)
{
    int idx = blockIdx.x * 256 + threadIdx.x;
    int i = idx >> 7, j = idx & 127;
    float s = 0.f;
#pragma unroll 1
    for (int h = 0; h < HEADS; h++) {
        const float* T = g_T + (size_t)h * ATTD * ATTD + i * ATTD;
        const float* W = W_att + (size_t)h * FIN * ATTD + j * ATTD;
#pragma unroll 8
        for (int k = 0; k < ATTD; k++) s += T[k] * W[k];
    }
    g_msum[i * FIN + j] = s;
}

// ---------------- vsum/usum/csum from W, A, b (1 block, 128 threads) -----------
__global__ void vec_kernel(const float* __restrict__ W_att,
                           const float* __restrict__ b_att,
                           const float* __restrict__ A_att)
{
    __shared__ float w1[ATTD], w2[ATTD], sb[ATTD], red[128];
    int t = threadIdx.x;
    float vs = 0.f, us = 0.f, cs = 0.f;
    for (int h = 0; h < HEADS; h++) {
        const float* A = A_att + (size_t)h * ATTD * ATTD;
        const float* W = W_att + (size_t)h * FIN * ATTD;
        sb[t] = b_att[h * ATTD + t];
        __syncthreads();
        float s1 = 0.f, s2 = 0.f;
        for (int j = 0; j < ATTD; j++) {
            s1 += A[t * ATTD + j] * sb[j];
            s2 += A[j * ATTD + t] * sb[j];
        }
        w1[t] = s1; w2[t] = s2;
        cs += sb[t] * s1;
        __syncthreads();
        float a1 = 0.f, a2 = 0.f;
        for (int k = 0; k < ATTD; k++) {
            a1 += W[t * ATTD + k] * w1[k];
            a2 += W[t * ATTD + k] * w2[k];
        }
        vs += a1; us += a2;
        __syncthreads();
    }
    g_vsum[t] = vs; g_usum[t] = us;
    red[t] = cs;
    __syncthreads();
    for (int o = 64; o; o >>= 1) {
        if (t < o) red[t] += red[t + o];
        __syncthreads();
    }
    if (t == 0) g_csum[0] = red[0];
    if (t < FIN) { g_bnsum[t] = 0.f; g_bnsq[t] = 0.f; }
}

// ------- conv_x: build A3 = [x_hi | x_lo | x_hi] AND per-node attn scalars -----
__global__ void convx_kernel(const float* __restrict__ x, int Nrows)
{
    __shared__ float sv[FIN], su[FIN];
    int tid = threadIdx.x;                  // 256
    if (tid < FIN) { sv[tid] = g_vsum[tid]; su[tid] = g_usum[tid]; }
    __syncthreads();
    int warp = tid >> 5, lane = tid & 31;
    int row = blockIdx.x * 8 + warp;
    if (row >= Nrows) return;

    float4 xv = ((const float4*)(x + (size_t)row * FIN))[lane];
    float4 v4 = ((const float4*)sv)[lane];
    float4 u4 = ((const float4*)su)[lane];
    float s1 = xv.x*v4.x + xv.y*v4.y + xv.z*v4.z + xv.w*v4.w;
    float s2 = xv.x*u4.x + xv.y*u4.y + xv.z*u4.z + xv.w*u4.w;

    // hi/lo split, packed as 4 bf16 = 8 bytes
    __nv_bfloat16 hp[4], lp[4];
    float vals[4] = {xv.x, xv.y, xv.z, xv.w};
#pragma unroll
    for (int c = 0; c < 4; c++) {
        __nv_bfloat16 h = __float2bfloat16(vals[c]);
        hp[c] = h;
        lp[c] = __float2bfloat16(vals[c] - __bfloat162float(h));
    }
    __nv_bfloat16* arow = g_A3 + (size_t)row * 384;
    *(uint2*)&arow[lane * 4]       = *(uint2*)hp;
    *(uint2*)&arow[128 + lane * 4] = *(uint2*)lp;
    *(uint2*)&arow[256 + lane * 4] = *(uint2*)hp;

#pragma unroll
    for (int o = 16; o; o >>= 1) {
        s1 += __shfl_xor_sync(0xffffffffu, s1, o);
        s2 += __shfl_xor_sync(0xffffffffu, s2, o);
    }
    if (lane == 0) { g_ar[row] = s1 + g_csum[0]; g_ac[row] = s2; }
}

// ------- conv_B: B3t[n][k'] n-major, paired with A3 term order -----------------
// term order over k': [0,128)=Bh, [128,256)=Bh, [256,384)=Bl ; Bc = [Msum | W_f1]
__global__ void convB_kernel(const float* __restrict__ W_f1)
{
    int idx = blockIdx.x * 256 + threadIdx.x;     // < 384*384
    int n = idx / 384, k3 = idx - n * 384;
    int k = k3 & 127;
    float v = (n < 128) ? g_msum[k * FIN + n] : W_f1[k * HIDDEN + (n - 128)];
    __nv_bfloat16 hi = __float2bfloat16(v);
    __nv_bfloat16 o = (k3 < 256) ? hi : __float2bfloat16(v - __bfloat162float(hi));
    g_B3t[(size_t)n * 384 + k3] = o;
}

// ================= fused Z + filtration GEMM, bf16 HMMA =======================
// C(N x 384) = A3(N x 384) @ B3t^T ; cols 0-127 -> g_z (plain),
// cols 128-383 -> g_h with relu(+b_f1). grid = (ceil(N/128), 3), 256 thr.
__global__ void __launch_bounds__(256, 2)
gemm_bf16(const float* __restrict__ bias, int Nrows)
{
    __shared__ __nv_bfloat16 As[2][128][40];
    __shared__ __nv_bfloat16 Bs[2][128][40];
    __shared__ float sbias[128];

    const int tid  = threadIdx.x;
    const int row0 = blockIdx.x * 128;
    const int n0   = blockIdx.y * 128;
    const bool isZ = (blockIdx.y == 0);
    if (!isZ && tid < 128) sbias[tid] = bias[n0 - 128 + tid];

    // global loaders: thread -> (row lr, 16-elem half lh)
    const int lr = tid >> 1;
    const int lh = tid & 1;
    const bool rok = (row0 + lr) < Nrows;
    const __nv_bfloat16* Ap = g_A3  + (size_t)(row0 + lr) * 384 + lh * 16;
    const __nv_bfloat16* Bp = g_B3t + (size_t)(n0   + lr) * 384 + lh * 16;

    uint4 a0q = make_uint4(0,0,0,0), a1q = a0q, b0q, b1q;
    if (rok) { a0q = *(const uint4*)Ap; a1q = *(const uint4*)(Ap + 8); }
    b0q = *(const uint4*)Bp; b1q = *(const uint4*)(Bp + 8);

    int buf = 0;
    *(uint4*)&As[0][lr][lh * 16]     = a0q;
    *(uint4*)&As[0][lr][lh * 16 + 8] = a1q;
    *(uint4*)&Bs[0][lr][lh * 16]     = b0q;
    *(uint4*)&Bs[0][lr][lh * 16 + 8] = b1q;
    __syncthreads();

    const int wid  = tid >> 5;
    const int lane = tid & 31;
    const int wm = wid >> 2;          // 0..1 : rows wm*64..+63
    const int wn = wid & 3;           // 0..3 : cols wn*32..+31
    const int g  = lane >> 2;         // 0..7
    const int t4 = lane & 3;          // 0..3

    float c[4][4][4];
#pragma unroll
    for (int mi = 0; mi < 4; mi++)
#pragma unroll
        for (int ni = 0; ni < 4; ni++)
#pragma unroll
            for (int q = 0; q < 4; q++) c[mi][ni][q] = 0.f;

    constexpr int NP = 384 / 32;      // 12 stages of BK=32
    for (int p = 0; p < NP; ++p) {
        if (p + 1 < NP) {
            const __nv_bfloat16* Apn = Ap + (p + 1) * 32;
            const __nv_bfloat16* Bpn = Bp + (p + 1) * 32;
            a0q = make_uint4(0,0,0,0); a1q = a0q;
            if (rok) { a0q = *(const uint4*)Apn; a1q = *(const uint4*)(Apn + 8); }
            b0q = *(const uint4*)Bpn; b1q = *(const uint4*)(Bpn + 8);
        }
#pragma unroll
        for (int kk = 0; kk < 32; kk += 16) {
            // B fragments: 4 n-tiles
            unsigned bf[4][2];
#pragma unroll
            for (int ni = 0; ni < 4; ni++) {
                int n = wn * 32 + ni * 8 + g;
                bf[ni][0] = *(const unsigned*)&Bs[buf][n][kk + 2 * t4];
                bf[ni][1] = *(const unsigned*)&Bs[buf][n][kk + 2 * t4 + 8];
            }
#pragma unroll
            for (int mi = 0; mi < 4; mi++) {
                int r = wm * 64 + mi * 16 + g;
                unsigned a0 = *(const unsigned*)&As[buf][r    ][kk + 2 * t4];
                unsigned a1 = *(const unsigned*)&As[buf][r + 8][kk + 2 * t4];
                unsigned a2 = *(const unsigned*)&As[buf][r    ][kk + 2 * t4 + 8];
                unsigned a3 = *(const unsigned*)&As[buf][r + 8][kk + 2 * t4 + 8];
#pragma unroll
                for (int ni = 0; ni < 4; ni++) {
                    asm volatile(
                        "mma.sync.aligned.m16n8k16.row.col.f32.bf16.bf16.f32 "
                        "{%0,%1,%2,%3}, {%4,%5,%6,%7}, {%8,%9}, {%0,%1,%2,%3};\n"
                        : "+f"(c[mi][ni][0]), "+f"(c[mi][ni][1]),
                          "+f"(c[mi][ni][2]), "+f"(c[mi][ni][3])
                        : "r"(a0), "r"(a1), "r"(a2), "r"(a3),
                          "r"(bf[ni][0]), "r"(bf[ni][1]));
                }
            }
        }
        if (p + 1 < NP) {
            buf ^= 1;
            *(uint4*)&As[buf][lr][lh * 16]     = a0q;
            *(uint4*)&As[buf][lr][lh * 16 + 8] = a1q;
            *(uint4*)&Bs[buf][lr][lh * 16]     = b0q;
            *(uint4*)&Bs[buf][lr][lh * 16 + 8] = b1q;
            __syncthreads();
        }
    }

    // epilogue
    __syncthreads();   // make sbias visible (written pre-loop, but be safe)
#pragma unroll
    for (int mi = 0; mi < 4; mi++) {
#pragma unroll
        for (int ni = 0; ni < 4; ni++) {
            int lcol = wn * 32 + ni * 8 + 2 * t4;
            int rA = row0 + wm * 64 + mi * 16 + g;
            int rB = rA + 8;
            float v0 = c[mi][ni][0], v1 = c[mi][ni][1];
            float v2 = c[mi][ni][2], v3 = c[mi][ni][3];
            if (isZ) {
                if (rA < Nrows) *(float2*)&g_z[(size_t)rA * FIN + lcol] = make_float2(v0, v1);
                if (rB < Nrows) *(float2*)&g_z[(size_t)rB * FIN + lcol] = make_float2(v2, v3);
            } else {
                int ch = n0 - 128 + lcol;
                float b0f = sbias[lcol], b1f = sbias[lcol + 1];
                if (rA < Nrows)
                    *(float2*)&g_h[(size_t)rA * HIDDEN + ch] =
                        make_float2(fmaxf(v0 + b0f, 0.f), fmaxf(v1 + b1f, 0.f));
                if (rB < Nrows)
                    *(float2*)&g_h[(size_t)rB * HIDDEN + ch] =
                        make_float2(fmaxf(v2 + b0f, 0.f), fmaxf(v3 + b1f, 0.f));
            }
        }
    }
}

// ---------------- single-pass edge score + sigmoid ----------------
__global__ void edge_kernel(const int* __restrict__ ei, const float* __restrict__ x,
                            float* __restrict__ out_att, int E_)
{
    int w = (blockIdx.x * blockDim.x + threadIdx.x) >> 5;
    int lane = threadIdx.x & 31;
    if (w >= E_) return;
    int r = ei[w];
    int c = ei[E_ + w];
    float4 a = ((const float4*)(g_z + (size_t)r * FIN))[lane];
    float4 b = ((const float4*)(x   + (size_t)c * FIN))[lane];
    float s = a.x * b.x + a.y * b.y + a.z * b.z + a.w * b.w;
#pragma unroll
    for (int o = 16; o; o >>= 1) s += __shfl_xor_sync(0xffffffffu, s, o);
    if (lane == 0) {
        float t = s + g_ar[r] + g_ac[c];
        out_att[w] = 1.f / (1.f + expf(-0.25f * t));
    }
}

// ---------------- fused fv + first set_fn layer (warp per row) ----------------
__global__ void filt2_kernel(const float* __restrict__ W_f2, const float* __restrict__ b_f2,
                             const float* __restrict__ W_l0, const float* __restrict__ b_l0,
                             int Nrows)
{
    __shared__ float sW2[HIDDEN * NFILT];
    __shared__ float sWe[NFILT * OUTD];
    __shared__ float sb2[NFILT];
    __shared__ float sbl[OUTD];

    int tid = threadIdx.x; // 256
    for (int i = tid; i < HIDDEN * NFILT; i += 256) sW2[i] = W_f2[i];
    for (int i = tid; i < NFILT * OUTD; i += 256) {
        int p = i / OUTD, c = i % OUTD;
        sWe[i] = W_l0[(2 * p) * OUTD + c] + W_l0[(2 * p + 1) * OUTD + c];
    }
    if (tid < NFILT) sb2[tid] = b_f2[tid];
    if (tid < OUTD)  sbl[tid] = b_l0[tid];
    __syncthreads();

    int warp = tid >> 5, lane = tid & 31;
    int row = blockIdx.x * 8 + warp;
    if (row >= Nrows) return;

    const float* hrow = g_h + (size_t)row * HIDDEN;
    float f[NFILT];
#pragma unroll
    for (int j = 0; j < NFILT; j++) f[j] = 0.f;
#pragma unroll
    for (int kk = 0; kk < HIDDEN / 32; kk++) {
        float hv = hrow[lane + kk * 32];
        const float* wrow = &sW2[(lane + kk * 32) * NFILT];
#pragma unroll
        for (int j = 0; j < NFILT; j++) f[j] += hv * wrow[j];
    }
#pragma unroll
    for (int o = 16; o; o >>= 1)
#pragma unroll
        for (int j = 0; j < NFILT; j++) f[j] += __shfl_xor_sync(0xffffffffu, f[j], o);
#pragma unroll
    for (int j = 0; j < NFILT; j++) f[j] += sb2[j];

    float* orow = g_x0a + (size_t)row * OUTD;
#pragma unroll
    for (int t = 0; t < 2; t++) {
        int c = lane + t * 32;
        float o = sbl[c];
#pragma unroll
        for (int j = 0; j < NFILT; j++) o += f[j] * sWe[j * OUTD + c];
        orow[c] = fmaxf(o, 0.f);
    }
}

// ---------------- segment boundaries (batch sorted) ----------------
__global__ void segbounds_kernel(const int* __restrict__ batch, int Nrows)
{
    int i = blockIdx.x * blockDim.x + threadIdx.x;
    if (i >= Nrows) return;
    int b = batch[i];
    int prev = (i == 0) ? -1 : batch[i - 1];
    for (int g = prev + 1; g <= b; ++g) g_segstart[g] = i;
    if (i == Nrows - 1)
        for (int g = b + 1; g <= GNUM; ++g) g_segstart[g] = Nrows;
}

// ---------------- fused segment mean + (mean @ L): xm (G x M) ----------------
template<int C, int M>
__global__ void segmeanL_kernel(const float* __restrict__ X, const float* __restrict__ L,
                                float* __restrict__ xm)
{
    const int T = 256;
    int g = blockIdx.x;
    int s = g_segstart[g], e = g_segstart[g + 1];
    int tid = threadIdx.x;
    int col = tid % C, rgrp = tid / C;
    const int ngrp = T / C;
    float acc = 0.f;
    for (int r = s + rgrp; r < e; r += ngrp) acc += X[(size_t)r * C + col];
    __shared__ float sh[T];
    __shared__ float smean[C];
    sh[tid] = acc;
    __syncthreads();
    if (tid < C) {
        float t = 0.f;
#pragma unroll
        for (int k = 0; k < ngrp; k++) t += sh[tid + k * C];
        smean[tid] = t / fmaxf((float)(e - s), 1.f);
    }
    __syncthreads();
    for (int j = tid; j < M; j += T) {
        float sm = 0.f;
#pragma unroll 8
        for (int k = 0; k < C; k++) sm += smean[k] * L[k * M + j];
        xm[g * M + j] = sm;
    }
}

// -------- final: out = x + (relu(x0c)-mu)*rstd*gamma + beta --------------------
__global__ void final_kernel(const float* __restrict__ x, const float* __restrict__ gamma,
                             const float* __restrict__ beta, float* __restrict__ out,
                             int Nrows)
{
    __shared__ float smu[FIN], srs[FIN], sg[FIN], sbt[FIN];
    int t = threadIdx.x; // 256
    if (t < FIN) {
        float inv = 1.f / (float)Nrows;
        float m = g_bnsum[t] * inv;
        float v = g_bnsq[t] * inv - m * m;
        smu[t] = m;
        srs[t] = rsqrtf(v + BN_EPS);
        sg[t] = gamma[t];
        sbt[t] = beta[t];
    }
    __syncthreads();
    int total = Nrows * FIN;
    for (int i = blockIdx.x * 256 + t; i < total; i += gridDim.x * 256) {
        int c = i & (FIN - 1);
        float h = fmaxf(g_x0c[i], 0.f);
        out[i] = x[i] + (h - smu[c]) * srs[c] * sg[c] + sbt[c];
    }
}

// ============================================================================
extern "C" void kernel_launch(void* const* d_in, const int* in_sizes, int n_in,
                              void* d_out, int out_size)
{
    const float* x       = (const float*)d_in[0];
    const int*   ei      = (const int*)  d_in[1];
    const int*   batch   = (const int*)  d_in[2];
    const float* W_f1    = (const float*)d_in[3];
    const float* b_f1    = (const float*)d_in[4];
    const float* W_f2    = (const float*)d_in[5];
    const float* b_f2    = (const float*)d_in[6];
    const float* W_l0    = (const float*)d_in[7];
    const float* b_l0    = (const float*)d_in[8];
    const float* G1      = (const float*)d_in[9];
    const float* b_g1    = (const float*)d_in[10];
    const float* L1      = (const float*)d_in[11];
    const float* G2      = (const float*)d_in[12];
    const float* b_g2    = (const float*)d_in[13];
    const float* L2      = (const float*)d_in[14];
    const float* bn_gamma= (const float*)d_in[15];
    const float* bn_beta = (const float*)d_in[16];
    const float* W_att   = (const float*)d_in[17];
    const float* b_att   = (const float*)d_in[18];
    const float* A_att   = (const float*)d_in[19];

    const int N = in_sizes[0] / FIN;
    const int E = in_sizes[1] / 2;

    float* out_x   = (float*)d_out;
    float* out_att = (float*)d_out + (size_t)N * FIN;

    float* h_p   = nullptr; cudaGetSymbolAddress((void**)&h_p,   g_h);
    float* x0a_p = nullptr; cudaGetSymbolAddress((void**)&x0a_p, g_x0a);
    float* x0b_p = nullptr; cudaGetSymbolAddress((void**)&x0b_p, g_x0b);
    float* x0c_p = nullptr; cudaGetSymbolAddress((void**)&x0c_p, g_x0c);
    float* T_p   = nullptr; cudaGetSymbolAddress((void**)&T_p,   g_T);
    float* xm1_p = nullptr; cudaGetSymbolAddress((void**)&xm1_p, g_xm1);
    float* xm2_p = nullptr; cudaGetSymbolAddress((void**)&xm2_p, g_xm2);

    const int gN = (N + 127) / 128;

    // ---- attention precompute: T_h = W_h @ A_h (all heads) ; Msum ; vecs ----
    gemm_big<ATTD, 0, true, false><<<dim3(1, 1, HEADS), 256>>>(
        W_att, A_att, nullptr, nullptr, nullptr, T_p, 128, ATTD, ATTD);
    msum_kernel<<<FIN * FIN / 256, 256>>>(W_att);
    vec_kernel<<<1, 128>>>(W_att, b_att, A_att);

    // ---- bf16 operand prep (conv_x also computes per-node scalars) ----
    convx_kernel<<<(N + 7) / 8, 256>>>(x, N);
    convB_kernel<<<(384 * 384) / 256, 256>>>(W_f1);

    // ---- fused Z + filtration GEMM on tensor cores ----
    gemm_bf16<<<dim3(gN, 3), 256>>>(b_f1, N);

    // ---- edge attention output ----
    edge_kernel<<<(E + 7) / 8, 256>>>(ei, x, out_att, E);

    // ---- filtration tail ----
    filt2_kernel<<<(N + 7) / 8, 256>>>(W_f2, b_f2, W_l0, b_l0, N);

    // ---- segment structure ----
    segbounds_kernel<<<(N + 255) / 256, 256>>>(batch, N);

    // ---- DeepSet 1 ----
    segmeanL_kernel<OUTD, OUTD><<<GNUM, 256>>>(x0a_p, L1, xm1_p);
    gemm128<OUTD, OUTD, 2><<<dim3(gN, 1), 256>>>(
        x0a_p, G1, b_g1, xm1_p, batch, x0b_p, N);

    // ---- DeepSet 2 (BN stats fused into epilogue) ----
    segmeanL_kernel<OUTD, FIN><<<GNUM, 256>>>(x0b_p, L2, xm2_p);
    gemm_big<OUTD, 3, false, true><<<dim3(gN, 1), 256>>>(
        x0b_p, G2, b_g2, xm2_p, batch, x0c_p, N, FIN, FIN);

    // ---- BatchNorm + residual ----
    final_kernel<<<1024, 256>>>(x, bn_gamma, bn_beta, out_x, N);
}

// round 16
// speedup vs baseline: 2.3065x; 1.0517x over previous
#include <cuda_runtime.h>
#include <cuda_bf16.h>
#include <math.h>

// Problem constants (fixed by the dataset)
#define NMAX   100000
#define EMAX   200000
#define GNUM   64
#define FIN    128
#define HIDDEN 256
#define NFILT  8
#define OUTD   64
#define ATTD   128
#define HEADS  4
#define BN_EPS 1e-5f

// ---------------- scratch (static device globals; no allocation) ----------------
__device__ float g_z  [(size_t)NMAX * FIN];    // x @ Msum
__device__ float g_x0a[(size_t)NMAX * OUTD];
__device__ float g_x0b[(size_t)NMAX * OUTD];
__device__ float g_x0c[(size_t)NMAX * FIN];
__device__ float g_ar [NMAX];                  // x·vsum + csum  (row term)
__device__ float g_ac [NMAX];                  // x·usum        (col term)
__device__ float g_T  [HEADS * ATTD * ATTD];   // per-head W@A
__device__ float g_msum[FIN * FIN];            // sum_h W A W^T
__device__ float g_vsum[FIN];
__device__ float g_usum[FIN];
__device__ float g_csum[1];
__device__ int   g_segstart[GNUM + 1];
__device__ float g_xm1[GNUM * OUTD];
__device__ float g_xm2[GNUM * FIN];
__device__ float g_bnsum[FIN];
__device__ float g_bnsq [FIN];
// bf16 split-precision B operand, n-major: k' order [Bh | Bh | Bl], Bc = [Msum | W_f1]
__device__ __nv_bfloat16 g_B3t[(size_t)384 * 384];

// ----- mega-kernel smem layout (dynamic, 106752 bytes) -----
#define SM_HI    0          // bf16[128][136]  34816
#define SM_LO    34816      // bf16[128][136]  34816
#define SM_B     69632      // bf16[2][128][40] 20480
#define SM_FV    90112      // f32[128][8]      4096
#define SM_W2    94208      // f32[256][8]      8192
#define SM_WE    102400     // f32[8][64]       2048
#define SM_BLX   104448     // f32[64]           256
#define SM_VU    104704     // f32[256]         1024
#define SM_BIAS  105728     // f32[256]         1024
#define SM_TOTAL 106752

// ================= 128x128-tile SGEMM (precompute + DS2) ======================
template<int K, int EPI, bool MULTI, bool STATS>
__global__ void __launch_bounds__(256, 2)
gemm_big(const float* __restrict__ A, const float* __restrict__ B,
         const float* __restrict__ bias, const float* __restrict__ xm,
         const int* __restrict__ batch, float* __restrict__ C,
         int Nrows, int Bld, int Cld)
{
    constexpr int BK = 8;
    constexpr int NP = K / BK;
    __shared__ float As[2][BK][132];
    __shared__ float Bs[2][BK][132];
    __shared__ float ssum[128];
    __shared__ float ssq [128];

    const int tid  = threadIdx.x;
    const int row0 = blockIdx.x * 128;
    const int col0 = blockIdx.y * 128;

    if (MULTI) {
        size_t z = blockIdx.z;
        A += z * 128 * K;
        B += z * (size_t)K * Bld;
        C += z * 128 * Cld;
    }
    if (STATS && tid < 128) { ssum[tid] = 0.f; ssq[tid] = 0.f; }

    const int ar = tid >> 1;
    const int ak = (tid & 1) * 4;
    const bool arow_ok = (row0 + ar) < Nrows;
    const float* Aptr = A + (size_t)(row0 + ar) * K + ak;

    const int bk = tid >> 5;
    const int bn = (tid & 31) * 4;
    const float* Bptr = B + (size_t)bk * Bld + col0 + bn;

    const int ty = tid >> 4;
    const int tx = tid & 15;

    float acc[8][8];
#pragma unroll
    for (int i = 0; i < 8; i++)
#pragma unroll
        for (int j = 0; j < 8; j++) acc[i][j] = 0.f;

    float4 a0 = make_float4(0.f,0.f,0.f,0.f), b0;
    if (arow_ok) a0 = *(const float4*)Aptr;
    b0 = *(const float4*)Bptr;

    int buf = 0;
    As[0][ak+0][ar] = a0.x; As[0][ak+1][ar] = a0.y;
    As[0][ak+2][ar] = a0.z; As[0][ak+3][ar] = a0.w;
    *(float4*)&Bs[0][bk][bn] = b0;
    __syncthreads();

    for (int p = 0; p < NP; ++p) {
        if (p + 1 < NP) {
            a0 = make_float4(0.f,0.f,0.f,0.f);
            if (arow_ok) a0 = *(const float4*)(Aptr + (p + 1) * BK);
            b0 = *(const float4*)(Bptr + (size_t)(p + 1) * BK * Bld);
        }
#pragma unroll
        for (int k = 0; k < BK; ++k) {
            float ra[8], rb[8];
            *(float4*)&ra[0] = *(const float4*)&As[buf][k][ty * 8];
            *(float4*)&ra[4] = *(const float4*)&As[buf][k][ty * 8 + 4];
            *(float4*)&rb[0] = *(const float4*)&Bs[buf][k][tx * 4];
            *(float4*)&rb[4] = *(const float4*)&Bs[buf][k][64 + tx * 4];
#pragma unroll
            for (int i = 0; i < 8; i++)
#pragma unroll
                for (int j = 0; j < 8; j++) acc[i][j] += ra[i] * rb[j];
        }
        if (p + 1 < NP) {
            buf ^= 1;
            As[buf][ak+0][ar] = a0.x; As[buf][ak+1][ar] = a0.y;
            As[buf][ak+2][ar] = a0.z; As[buf][ak+3][ar] = a0.w;
            *(float4*)&Bs[buf][bk][bn] = b0;
            __syncthreads();
        }
    }

    float cs[8], cq[8];
    if (STATS) {
#pragma unroll
        for (int j = 0; j < 8; j++) { cs[j] = 0.f; cq[j] = 0.f; }
    }
    const int rbase = row0 + ty * 8;
#pragma unroll
    for (int i = 0; i < 8; i++) {
        int r = rbase + i;
        if (r >= Nrows) continue;
        int bidx = 0;
        if (EPI >= 2) bidx = batch[r];
        float v[8];
#pragma unroll
        for (int j = 0; j < 8; j++) {
            int c = col0 + ((j < 4) ? (tx * 4 + j) : (64 + tx * 4 + j - 4));
            float t = acc[i][j];
            if (bias) t += bias[c];
            if (EPI >= 2) t -= xm[bidx * Cld + c];
            if (EPI == 1 || EPI == 2) t = fmaxf(t, 0.f);
            v[j] = t;
            if (STATS) {
                float rv = fmaxf(t, 0.f);
                cs[j] += rv; cq[j] += rv * rv;
            }
        }
        float* Crow = C + (size_t)r * Cld + col0;
        *(float4*)&Crow[tx * 4]      = make_float4(v[0], v[1], v[2], v[3]);
        *(float4*)&Crow[64 + tx * 4] = make_float4(v[4], v[5], v[6], v[7]);
    }
    if (STATS) {
#pragma unroll
        for (int j = 0; j < 8; j++) {
            int ct = (j < 4) ? (tx * 4 + j) : (64 + tx * 4 + j - 4);
            atomicAdd(&ssum[ct], cs[j]);
            atomicAdd(&ssq[ct],  cq[j]);
        }
        __syncthreads();
        if (tid < 128) {
            atomicAdd(&g_bnsum[col0 + tid], ssum[tid]);
            atomicAdd(&g_bnsq [col0 + tid], ssq[tid]);
        }
    }
}

// ---------------- 128x64-tile SGEMM (DeepSet1), BK=16 ----------------
template<int K, int M, int EPI>
__global__ void __launch_bounds__(256)
gemm128(const float* __restrict__ A, const float* __restrict__ B,
        const float* __restrict__ bias, const float* __restrict__ xm,
        const int* __restrict__ batch, float* __restrict__ C, int Nrows)
{
    constexpr int BK = 16;
    constexpr int NP = K / BK;
    __shared__ float As[2][BK][132];
    __shared__ float Bs[2][BK][68];

    const int tid  = threadIdx.x;
    const int row0 = blockIdx.x * 128;
    const int col0 = blockIdx.y * 64;

    const int ar = tid & 127;
    const int ak = (tid >> 7) * 8;
    const bool arow_ok = (row0 + ar) < Nrows;
    const float* Aptr = A + (size_t)(row0 + ar) * K + ak;

    const int bk = tid >> 4;
    const int bn = (tid & 15) * 4;
    const float* Bptr = B + (size_t)bk * M + col0 + bn;

    const int ty = tid >> 4;
    const int tx = tid & 15;

    float acc[8][4];
#pragma unroll
    for (int i = 0; i < 8; i++)
#pragma unroll
        for (int j = 0; j < 4; j++) acc[i][j] = 0.f;

    float4 a0 = make_float4(0.f,0.f,0.f,0.f), a1 = a0, b0;
    if (arow_ok) { a0 = *(const float4*)Aptr; a1 = *(const float4*)(Aptr + 4); }
    b0 = *(const float4*)Bptr;

    int buf = 0;
    As[0][ak+0][ar] = a0.x; As[0][ak+1][ar] = a0.y;
    As[0][ak+2][ar] = a0.z; As[0][ak+3][ar] = a0.w;
    As[0][ak+4][ar] = a1.x; As[0][ak+5][ar] = a1.y;
    As[0][ak+6][ar] = a1.z; As[0][ak+7][ar] = a1.w;
    *(float4*)&Bs[0][bk][bn] = b0;
    __syncthreads();

    for (int p = 0; p < NP; ++p) {
        if (p + 1 < NP) {
            const float* Ap = Aptr + (p + 1) * BK;
            a0 = make_float4(0.f,0.f,0.f,0.f); a1 = a0;
            if (arow_ok) { a0 = *(const float4*)Ap; a1 = *(const float4*)(Ap + 4); }
            b0 = *(const float4*)(Bptr + (size_t)(p + 1) * BK * M);
        }
#pragma unroll
        for (int k = 0; k < BK; ++k) {
            float ra[8], rb[4];
            *(float4*)&ra[0] = *(const float4*)&As[buf][k][ty * 8];
            *(float4*)&ra[4] = *(const float4*)&As[buf][k][ty * 8 + 4];
            *(float4*)&rb[0] = *(const float4*)&Bs[buf][k][tx * 4];
#pragma unroll
            for (int i = 0; i < 8; i++)
#pragma unroll
                for (int j = 0; j < 4; j++) acc[i][j] += ra[i] * rb[j];
        }
        if (p + 1 < NP) {
            buf ^= 1;
            As[buf][ak+0][ar] = a0.x; As[buf][ak+1][ar] = a0.y;
            As[buf][ak+2][ar] = a0.z; As[buf][ak+3][ar] = a0.w;
            As[buf][ak+4][ar] = a1.x; As[buf][ak+5][ar] = a1.y;
            As[buf][ak+6][ar] = a1.z; As[buf][ak+7][ar] = a1.w;
            *(float4*)&Bs[buf][bk][bn] = b0;
            __syncthreads();
        }
    }

    const int rbase = row0 + ty * 8;
    const int cbase = col0 + tx * 4;
#pragma unroll
    for (int i = 0; i < 8; i++) {
        int r = rbase + i;
        if (r >= Nrows) continue;
        int bidx = 0;
        if (EPI >= 2) bidx = batch[r];
#pragma unroll
        for (int j = 0; j < 4; j++) {
            int c = cbase + j;
            float v = acc[i][j];
            if (bias) v += bias[c];
            if (EPI >= 2) v -= xm[bidx * M + c];
            if (EPI == 1 || EPI == 2) v = fmaxf(v, 0.f);
            C[(size_t)r * M + c] = v;
        }
    }
}

// ---------------- Msum[i][j] = sum_h sum_k T_h[i][k] * W_h[j][k] ----------------
__global__ void msum_kernel(const float* __restrict__ W_att)
{
    int idx = blockIdx.x * 256 + threadIdx.x;
    int i = idx >> 7, j = idx & 127;
    float s = 0.f;
#pragma unroll 1
    for (int h = 0; h < HEADS; h++) {
        const float* T = g_T + (size_t)h * ATTD * ATTD + i * ATTD;
        const float* W = W_att + (size_t)h * FIN * ATTD + j * ATTD;
#pragma unroll 8
        for (int k = 0; k < ATTD; k++) s += T[k] * W[k];
    }
    g_msum[i * FIN + j] = s;
}

// ---------------- vsum/usum/csum from W, A, b (1 block, 128 threads) -----------
__global__ void vec_kernel(const float* __restrict__ W_att,
                           const float* __restrict__ b_att,
                           const float* __restrict__ A_att)
{
    __shared__ float w1[ATTD], w2[ATTD], sb[ATTD], red[128];
    int t = threadIdx.x;
    float vs = 0.f, us = 0.f, cs = 0.f;
    for (int h = 0; h < HEADS; h++) {
        const float* A = A_att + (size_t)h * ATTD * ATTD;
        const float* W = W_att + (size_t)h * FIN * ATTD;
        sb[t] = b_att[h * ATTD + t];
        __syncthreads();
        float s1 = 0.f, s2 = 0.f;
        for (int j = 0; j < ATTD; j++) {
            s1 += A[t * ATTD + j] * sb[j];
            s2 += A[j * ATTD + t] * sb[j];
        }
        w1[t] = s1; w2[t] = s2;
        cs += sb[t] * s1;
        __syncthreads();
        float a1 = 0.f, a2 = 0.f;
        for (int k = 0; k < ATTD; k++) {
            a1 += W[t * ATTD + k] * w1[k];
            a2 += W[t * ATTD + k] * w2[k];
        }
        vs += a1; us += a2;
        __syncthreads();
    }
    g_vsum[t] = vs; g_usum[t] = us;
    red[t] = cs;
    __syncthreads();
    for (int o = 64; o; o >>= 1) {
        if (t < o) red[t] += red[t + o];
        __syncthreads();
    }
    if (t == 0) g_csum[0] = red[0];
    if (t < FIN) { g_bnsum[t] = 0.f; g_bnsq[t] = 0.f; }
}

// ------- conv_B: B3t[n][k'] n-major; k' order [Bh | Bh | Bl]; Bc = [Msum | W_f1]
__global__ void convB_kernel(const float* __restrict__ W_f1)
{
    int idx = blockIdx.x * 256 + threadIdx.x;     // < 384*384
    int n = idx / 384, k3 = idx - n * 384;
    int k = k3 & 127;
    float v = (n < 128) ? g_msum[k * FIN + n] : W_f1[k * HIDDEN + (n - 128)];
    __nv_bfloat16 hi = __float2bfloat16(v);
    __nv_bfloat16 o = (k3 < 256) ? hi : __float2bfloat16(v - __bfloat162float(hi));
    g_B3t[(size_t)n * 384 + k3] = o;
}

// ================= MEGA: x->hi/lo (smem) -> z + h -> fv -> x0a =================
// grid = (ceil(N/128)), 256 threads, dynamic smem SM_TOTAL.
__global__ void __launch_bounds__(256, 2)
mega_kernel(const float* __restrict__ x, const float* __restrict__ b_f1,
            const float* __restrict__ W_f2, const float* __restrict__ b_f2,
            const float* __restrict__ W_l0, const float* __restrict__ b_l0,
            int Nrows)
{
    extern __shared__ __align__(16) char smem[];
    __nv_bfloat16* s_hi = (__nv_bfloat16*)(smem + SM_HI);   // [128][136]
    __nv_bfloat16* s_lo = (__nv_bfloat16*)(smem + SM_LO);   // [128][136]
    __nv_bfloat16* s_B  = (__nv_bfloat16*)(smem + SM_B);    // [2][128][40]
    float* s_fv  = (float*)(smem + SM_FV);    // [128][8]
    float* s_w2  = (float*)(smem + SM_W2);    // [256][8]
    float* s_we  = (float*)(smem + SM_WE);    // [8][64]
    float* s_blx = (float*)(smem + SM_BLX);   // [64]
    float* s_vu  = (float*)(smem + SM_VU);    // [256] = vsum|usum
    float* s_bias= (float*)(smem + SM_BIAS);  // [256]

    const int tid  = threadIdx.x;
    const int row0 = blockIdx.x * 128;

    // ---- phase 0: constants + zero fv ----
    if (tid < 128) { s_vu[tid] = g_vsum[tid]; s_vu[128 + tid] = g_usum[tid]; }
    s_bias[tid] = b_f1[tid];
    for (int i = tid; i < HIDDEN * NFILT; i += 256) s_w2[i] = W_f2[i];
    for (int i = tid; i < NFILT * OUTD; i += 256) {
        int p = i >> 6, c = i & 63;
        s_we[i] = W_l0[(2 * p) * OUTD + c] + W_l0[(2 * p + 1) * OUTD + c];
    }
    ((float4*)s_fv)[tid] = make_float4(0.f, 0.f, 0.f, 0.f);
    __syncthreads();
    if (tid < OUTD) {
        float v = b_l0[tid];
#pragma unroll
        for (int j = 0; j < NFILT; j++) v += b_f2[j] * s_we[j * OUTD + tid];
        s_blx[tid] = v;
    }

    // ---- phase 1: load x tile, split hi/lo into smem, node scalars ----
    {
        const int lr = tid >> 1, lh = tid & 1;
        const int grow = row0 + lr;
        const bool rok = grow < Nrows;
        const float4* xr = (const float4*)(x + (size_t)grow * FIN + lh * 64);
        float s1 = 0.f, s2 = 0.f;
#pragma unroll
        for (int i = 0; i < 16; i++) {
            float4 v = rok ? xr[i] : make_float4(0.f, 0.f, 0.f, 0.f);
            int c = lh * 64 + i * 4;
            s1 += v.x * s_vu[c] + v.y * s_vu[c+1] + v.z * s_vu[c+2] + v.w * s_vu[c+3];
            s2 += v.x * s_vu[128+c] + v.y * s_vu[129+c] + v.z * s_vu[130+c] + v.w * s_vu[131+c];
            __nv_bfloat16 hp[4], lp[4];
            float vals[4] = {v.x, v.y, v.z, v.w};
#pragma unroll
            for (int q = 0; q < 4; q++) {
                __nv_bfloat16 h = __float2bfloat16(vals[q]);
                hp[q] = h;
                lp[q] = __float2bfloat16(vals[q] - __bfloat162float(h));
            }
            *(uint2*)&s_hi[lr * 136 + c] = *(uint2*)hp;
            *(uint2*)&s_lo[lr * 136 + c] = *(uint2*)lp;
        }
        s1 += __shfl_xor_sync(0xffffffffu, s1, 1);
        s2 += __shfl_xor_sync(0xffffffffu, s2, 1);
        if (rok && lh == 0) { g_ar[grow] = s1 + g_csum[0]; g_ac[grow] = s2; }
    }

    // ---- phase 2: GEMM over 3 col tiles (z | h0 | h1) ----
    const int lane = tid & 31, wid = tid >> 5;
    const int wm = wid >> 2, wn = wid & 3;
    const int gg = lane >> 2, t4 = lane & 3;
    const int brow = tid >> 1, bh = tid & 1;

    uint4 pb0, pb1;
    {
        const __nv_bfloat16* p = g_B3t + (size_t)brow * 384 + bh * 16;
        pb0 = *(const uint4*)p; pb1 = *(const uint4*)(p + 8);
    }
    *(uint4*)&s_B[(size_t)brow * 40 + bh * 16]     = pb0;
    *(uint4*)&s_B[(size_t)brow * 40 + bh * 16 + 8] = pb1;
    __syncthreads();

    int buf = 0;
    for (int tile = 0; tile < 3; tile++) {
        float acc[4][4][4];
#pragma unroll
        for (int mi = 0; mi < 4; mi++)
#pragma unroll
            for (int ni = 0; ni < 4; ni++)
#pragma unroll
                for (int q = 0; q < 4; q++) acc[mi][ni][q] = 0.f;

        for (int kc = 0; kc < 12; kc++) {
            int cc = tile * 12 + kc;
            if (cc < 35) {
                int nt = (cc + 1) / 12, nk = (cc + 1) % 12;
                const __nv_bfloat16* p =
                    g_B3t + (size_t)(nt * 128 + brow) * 384 + nk * 32 + bh * 16;
                pb0 = *(const uint4*)p; pb1 = *(const uint4*)(p + 8);
            }
            const __nv_bfloat16* Asrc = (kc >= 4 && kc < 8) ? s_lo : s_hi;
            const int kbase = (kc & 3) * 32;
            const __nv_bfloat16* Bb = s_B + buf * (128 * 40);
#pragma unroll
            for (int kk = 0; kk < 32; kk += 16) {
                unsigned bfr[4][2];
#pragma unroll
                for (int ni = 0; ni < 4; ni++) {
                    int n = wn * 32 + ni * 8 + gg;
                    bfr[ni][0] = *(const unsigned*)&Bb[n * 40 + kk + 2 * t4];
                    bfr[ni][1] = *(const unsigned*)&Bb[n * 40 + kk + 2 * t4 + 8];
                }
#pragma unroll
                for (int mi = 0; mi < 4; mi++) {
                    int r = wm * 64 + mi * 16 + gg;
                    unsigned a0 = *(const unsigned*)&Asrc[r * 136 + kbase + kk + 2 * t4];
                    unsigned a1 = *(const unsigned*)&Asrc[(r + 8) * 136 + kbase + kk + 2 * t4];
                    unsigned a2 = *(const unsigned*)&Asrc[r * 136 + kbase + kk + 2 * t4 + 8];
                    unsigned a3 = *(const unsigned*)&Asrc[(r + 8) * 136 + kbase + kk + 2 * t4 + 8];
#pragma unroll
                    for (int ni = 0; ni < 4; ni++) {
                        asm volatile(
                            "mma.sync.aligned.m16n8k16.row.col.f32.bf16.bf16.f32 "
                            "{%0,%1,%2,%3}, {%4,%5,%6,%7}, {%8,%9}, {%0,%1,%2,%3};\n"
                            : "+f"(acc[mi][ni][0]), "+f"(acc[mi][ni][1]),
                              "+f"(acc[mi][ni][2]), "+f"(acc[mi][ni][3])
                            : "r"(a0), "r"(a1), "r"(a2), "r"(a3),
                              "r"(bfr[ni][0]), "r"(bfr[ni][1]));
                    }
                }
            }
            if (cc < 35) {
                buf ^= 1;
                *(uint4*)&s_B[(size_t)(buf * 128 + brow) * 40 + bh * 16]     = pb0;
                *(uint4*)&s_B[(size_t)(buf * 128 + brow) * 40 + bh * 16 + 8] = pb1;
                __syncthreads();
            }
        }

        // ---- tile epilogue ----
        if (tile == 0) {
            // z tile: plain fp32 store
#pragma unroll
            for (int mi = 0; mi < 4; mi++) {
#pragma unroll
                for (int ni = 0; ni < 4; ni++) {
                    int lcol = wn * 32 + ni * 8 + 2 * t4;
                    int rA = row0 + wm * 64 + mi * 16 + gg;
                    int rB = rA + 8;
                    if (rA < Nrows)
                        *(float2*)&g_z[(size_t)rA * FIN + lcol] =
                            make_float2(acc[mi][ni][0], acc[mi][ni][1]);
                    if (rB < Nrows)
                        *(float2*)&g_z[(size_t)rB * FIN + lcol] =
                            make_float2(acc[mi][ni][2], acc[mi][ni][3]);
                }
            }
        } else {
            // h tile: relu(+bias) then fold into fv partials (never stored)
            const int ch_base = (tile - 1) * 128;
#pragma unroll
            for (int mi = 0; mi < 4; mi++) {
                float fr[2][NFILT];
#pragma unroll
                for (int j = 0; j < NFILT; j++) { fr[0][j] = 0.f; fr[1][j] = 0.f; }
#pragma unroll
                for (int ni = 0; ni < 4; ni++) {
                    int lcol = wn * 32 + ni * 8 + 2 * t4;
                    int c0 = ch_base + lcol, c1 = c0 + 1;
                    float hA0 = fmaxf(acc[mi][ni][0] + s_bias[lcol],     0.f);
                    float hA1 = fmaxf(acc[mi][ni][1] + s_bias[lcol + 1], 0.f);
                    float hB0 = fmaxf(acc[mi][ni][2] + s_bias[lcol],     0.f);
                    float hB1 = fmaxf(acc[mi][ni][3] + s_bias[lcol + 1], 0.f);
#pragma unroll
                    for (int j = 0; j < NFILT; j++) {
                        fr[0][j] += hA0 * s_w2[c0 * NFILT + j] + hA1 * s_w2[c1 * NFILT + j];
                        fr[1][j] += hB0 * s_w2[c0 * NFILT + j] + hB1 * s_w2[c1 * NFILT + j];
                    }
                }
#pragma unroll
                for (int j = 0; j < NFILT; j++) {
                    fr[0][j] += __shfl_xor_sync(0xffffffffu, fr[0][j], 1);
                    fr[0][j] += __shfl_xor_sync(0xffffffffu, fr[0][j], 2);
                    fr[1][j] += __shfl_xor_sync(0xffffffffu, fr[1][j], 1);
                    fr[1][j] += __shfl_xor_sync(0xffffffffu, fr[1][j], 2);
                }
                if (t4 == 0) {
                    int lrA = wm * 64 + mi * 16 + gg;
#pragma unroll
                    for (int j = 0; j < NFILT; j++) {
                        atomicAdd(&s_fv[lrA * NFILT + j],       fr[0][j]);
                        atomicAdd(&s_fv[(lrA + 8) * NFILT + j], fr[1][j]);
                    }
                }
            }
        }
    }

    // ---- phase 3: x0a = relu(fv @ Weff + blx) ----
    __syncthreads();
    for (int idx = tid; idx < 128 * OUTD; idx += 256) {
        int r = idx >> 6, c = idx & 63;
        int grow = row0 + r;
        if (grow >= Nrows) continue;
        float v = s_blx[c];
#pragma unroll
        for (int j = 0; j < NFILT; j++) v += s_fv[r * NFILT + j] * s_we[j * OUTD + c];
        g_x0a[(size_t)grow * OUTD + c] = fmaxf(v, 0.f);
    }
}

// ---------------- single-pass edge score + sigmoid ----------------
__global__ void edge_kernel(const int* __restrict__ ei, const float* __restrict__ x,
                            float* __restrict__ out_att, int E_)
{
    int w = (blockIdx.x * blockDim.x + threadIdx.x) >> 5;
    int lane = threadIdx.x & 31;
    if (w >= E_) return;
    int r = ei[w];
    int c = ei[E_ + w];
    float4 a = ((const float4*)(g_z + (size_t)r * FIN))[lane];
    float4 b = ((const float4*)(x   + (size_t)c * FIN))[lane];
    float s = a.x * b.x + a.y * b.y + a.z * b.z + a.w * b.w;
#pragma unroll
    for (int o = 16; o; o >>= 1) s += __shfl_xor_sync(0xffffffffu, s, o);
    if (lane == 0) {
        float t = s + g_ar[r] + g_ac[c];
        out_att[w] = 1.f / (1.f + expf(-0.25f * t));
    }
}

// ---------------- segment boundaries (batch sorted) ----------------
__global__ void segbounds_kernel(const int* __restrict__ batch, int Nrows)
{
    int i = blockIdx.x * blockDim.x + threadIdx.x;
    if (i >= Nrows) return;
    int b = batch[i];
    int prev = (i == 0) ? -1 : batch[i - 1];
    for (int g = prev + 1; g <= b; ++g) g_segstart[g] = i;
    if (i == Nrows - 1)
        for (int g = b + 1; g <= GNUM; ++g) g_segstart[g] = Nrows;
}

// ---------------- fused segment mean + (mean @ L): xm (G x M) ----------------
template<int C, int M>
__global__ void segmeanL_kernel(const float* __restrict__ X, const float* __restrict__ L,
                                float* __restrict__ xm)
{
    const int T = 256;
    int g = blockIdx.x;
    int s = g_segstart[g], e = g_segstart[g + 1];
    int tid = threadIdx.x;
    int col = tid % C, rgrp = tid / C;
    const int ngrp = T / C;
    float acc = 0.f;
    for (int r = s + rgrp; r < e; r += ngrp) acc += X[(size_t)r * C + col];
    __shared__ float sh[T];
    __shared__ float smean[C];
    sh[tid] = acc;
    __syncthreads();
    if (tid < C) {
        float t = 0.f;
#pragma unroll
        for (int k = 0; k < ngrp; k++) t += sh[tid + k * C];
        smean[tid] = t / fmaxf((float)(e - s), 1.f);
    }
    __syncthreads();
    for (int j = tid; j < M; j += T) {
        float sm = 0.f;
#pragma unroll 8
        for (int k = 0; k < C; k++) sm += smean[k] * L[k * M + j];
        xm[g * M + j] = sm;
    }
}

// -------- final: out = x + (relu(x0c)-mu)*rstd*gamma + beta --------------------
__global__ void final_kernel(const float* __restrict__ x, const float* __restrict__ gamma,
                             const float* __restrict__ beta, float* __restrict__ out,
                             int Nrows)
{
    __shared__ float smu[FIN], srs[FIN], sg[FIN], sbt[FIN];
    int t = threadIdx.x; // 256
    if (t < FIN) {
        float inv = 1.f / (float)Nrows;
        float m = g_bnsum[t] * inv;
        float v = g_bnsq[t] * inv - m * m;
        smu[t] = m;
        srs[t] = rsqrtf(v + BN_EPS);
        sg[t] = gamma[t];
        sbt[t] = beta[t];
    }
    __syncthreads();
    int total = Nrows * FIN;
    for (int i = blockIdx.x * 256 + t; i < total; i += gridDim.x * 256) {
        int c = i & (FIN - 1);
        float h = fmaxf(g_x0c[i], 0.f);
        out[i] = x[i] + (h - smu[c]) * srs[c] * sg[c] + sbt[c];
    }
}

// ============================================================================
extern "C" void kernel_launch(void* const* d_in, const int* in_sizes, int n_in,
                              void* d_out, int out_size)
{
    const float* x       = (const float*)d_in[0];
    const int*   ei      = (const int*)  d_in[1];
    const int*   batch   = (const int*)  d_in[2];
    const float* W_f1    = (const float*)d_in[3];
    const float* b_f1    = (const float*)d_in[4];
    const float* W_f2    = (const float*)d_in[5];
    const float* b_f2    = (const float*)d_in[6];
    const float* W_l0    = (const float*)d_in[7];
    const float* b_l0    = (const float*)d_in[8];
    const float* G1      = (const float*)d_in[9];
    const float* b_g1    = (const float*)d_in[10];
    const float* L1      = (const float*)d_in[11];
    const float* G2      = (const float*)d_in[12];
    const float* b_g2    = (const float*)d_in[13];
    const float* L2      = (const float*)d_in[14];
    const float* bn_gamma= (const float*)d_in[15];
    const float* bn_beta = (const float*)d_in[16];
    const float* W_att   = (const float*)d_in[17];
    const float* b_att   = (const float*)d_in[18];
    const float* A_att   = (const float*)d_in[19];

    const int N = in_sizes[0] / FIN;
    const int E = in_sizes[1] / 2;

    float* out_x   = (float*)d_out;
    float* out_att = (float*)d_out + (size_t)N * FIN;

    float* x0a_p = nullptr; cudaGetSymbolAddress((void**)&x0a_p, g_x0a);
    float* x0b_p = nullptr; cudaGetSymbolAddress((void**)&x0b_p, g_x0b);
    float* x0c_p = nullptr; cudaGetSymbolAddress((void**)&x0c_p, g_x0c);
    float* T_p   = nullptr; cudaGetSymbolAddress((void**)&T_p,   g_T);
    float* xm1_p = nullptr; cudaGetSymbolAddress((void**)&xm1_p, g_xm1);
    float* xm2_p = nullptr; cudaGetSymbolAddress((void**)&xm2_p, g_xm2);

    static bool attr_done = false;
    if (!attr_done) {
        cudaFuncSetAttribute(mega_kernel,
                             cudaFuncAttributeMaxDynamicSharedMemorySize, SM_TOTAL);
        attr_done = true;
    }

    const int gN = (N + 127) / 128;

    // ---- attention precompute: T_h = W_h @ A_h (all heads) ; Msum ; vecs ----
    gemm_big<ATTD, 0, true, false><<<dim3(1, 1, HEADS), 256>>>(
        W_att, A_att, nullptr, nullptr, nullptr, T_p, 128, ATTD, ATTD);
    msum_kernel<<<FIN * FIN / 256, 256>>>(W_att);
    vec_kernel<<<1, 128>>>(W_att, b_att, A_att);
    convB_kernel<<<(384 * 384) / 256, 256>>>(W_f1);

    // ---- independent small kernel: segment bounds ----
    segbounds_kernel<<<(N + 255) / 256, 256>>>(batch, N);

    // ---- MEGA: z + node scalars + filtration head + x0a, one kernel ----
    mega_kernel<<<gN, 256, SM_TOTAL>>>(x, b_f1, W_f2, b_f2, W_l0, b_l0, N);

    // ---- edge attention output ----
    edge_kernel<<<(E + 7) / 8, 256>>>(ei, x, out_att, E);

    // ---- DeepSet 1 ----
    segmeanL_kernel<OUTD, OUTD><<<GNUM, 256>>>(x0a_p, L1, xm1_p);
    gemm128<OUTD, OUTD, 2><<<dim3(gN, 1), 256>>>(
        x0a_p, G1, b_g1, xm1_p, batch, x0b_p, N);

    // ---- DeepSet 2 (BN stats fused into epilogue) ----
    segmeanL_kernel<OUTD, FIN><<<GNUM, 256>>>(x0b_p, L2, xm2_p);
    gemm_big<OUTD, 3, false, true><<<dim3(gN, 1), 256>>>(
        x0b_p, G2, b_g2, xm2_p, batch, x0c_p, N, FIN, FIN);

    // ---- BatchNorm + residual ----
    final_kernel<<<1024, 256>>>(x, bn_gamma, bn_beta, out_x, N);
}